// round 10
// baseline (speedup 1.0000x reference)
#include <cuda_runtime.h>
#include <cuda_fp16.h>
#include <cstdint>

// ---------------- problem constants ----------------
#define T_WIN 4
#define BATCH 128
#define SEQ   64
#define BSROWS 8192           // BATCH*SEQ
#define DIN   3136
#define FUS   512
#define HID   512
#define NLAST 18
#define MROWS (T_WIN*BSROWS)  // 32768
#define NELEM (BSROWS*FUS)    // 4,194,304 soma elements

// ---------------- fp16 GEMM tiling (2-product: C = A * (Bh + Bl)) ----------------
#define HBM 128
#define HBN 256
#define HBK 32
#define HSTR 40                              // halves per smem row (32 + 8 pad)
#define H_OFF_B0 (128*HSTR)
#define H_OFF_B1 ((128+256)*HSTR)
#define H_STAGE  ((128+512)*HSTR)            // 25600 halves = 51200 B
#define NSTAGE 4
#define HGEMM_SMEM (NSTAGE*H_STAGE*2)        // 204800 B

#define DELTA0 2e-3f          // soma flag band scale (dist err sigma ~2.8e-4, >=25 sigma... per (1+pm))
#define DELTA2 2e-4f          // layer-2 flag band (h err ~5e-6)

// ---------------- scratch (device globals; no allocations allowed) ----------------
__device__ __half        g_Ah  [(size_t)MROWS * DIN];             // 205 MiB (fp16 of tau)
__device__ __half        g_WhT [(size_t)FUS * DIN];               // W_dist^T fp16-hi
__device__ __half        g_WlT [(size_t)FUS * DIN];               // W_dist^T fp16-lo
__device__ float         g_WT  [(size_t)FUS * DIN];               // exact fp32 W_dist^T (repair1)
__device__ __half        g_W1hT[(size_t)HID * FUS];               // W1^T fp16-hi
__device__ __half        g_W1lT[(size_t)HID * FUS];               // W1^T fp16-lo
__device__ float         g_W1T [(size_t)HID * FUS];               // exact fp32 W1^T (repair2)
__device__ float         g_dist [(size_t)T_WIN * BSROWS * FUS];   // 64 MiB
__device__ float         g_hfast[(size_t)MROWS * HID];            // 64 MiB
__device__ float         g_prox [T_WIN * BATCH * FUS];
__device__ float         g_trunk[T_WIN * BATCH * FUS];
__device__ float         g_pall [T_WIN * BATCH * FUS];
__device__ float         g_tall [T_WIN * BATCH * FUS];
__device__ unsigned char g_spk  [(size_t)T_WIN * NELEM];          // 16 MiB (layer-1 spikes)
__device__ __half        g_spkh [(size_t)T_WIN * NELEM];          // 32 MiB (same, fp16 for MMA)
__device__ unsigned char g_flag [NELEM];                          // soma near-threshold flags
__device__ unsigned char g_hs4  [(size_t)T_WIN * NELEM];          // 16 MiB (layer-2 spikes, all t)
__device__ unsigned char g_flag2[NELEM];                          // layer-2 flags
__device__ float         g_outacc[BSROWS * NLAST];

// ---------------- helpers ----------------
__device__ __forceinline__ uint32_t s2u(const void* p) {
    uint32_t a;
    asm("{ .reg .u64 t; cvta.to.shared.u64 t, %1; cvt.u32.u64 %0, t; }" : "=r"(a) : "l"(p));
    return a;
}
__device__ __forceinline__ void cp16(uint32_t dst, const void* src) {
    asm volatile("cp.async.cg.shared.global [%0], [%1], 16;" :: "r"(dst), "l"(src));
}
// D += A(f16) * B(f16), fp32 accum; m16n8k16, A row-major, B col-major
__device__ __forceinline__ void hmma16(float* c, const uint32_t* a, uint32_t b0, uint32_t b1) {
    asm volatile(
        "mma.sync.aligned.m16n8k16.row.col.f32.f16.f16.f32 "
        "{%0,%1,%2,%3}, {%4,%5,%6,%7}, {%8,%9}, {%0,%1,%2,%3};"
        : "+f"(c[0]), "+f"(c[1]), "+f"(c[2]), "+f"(c[3])
        : "r"(a[0]), "r"(a[1]), "r"(a[2]), "r"(a[3]), "r"(b0), "r"(b1));
}
__device__ __forceinline__ uint32_t pack2(__half lo, __half hi) {
    return (uint32_t)__half_as_ushort(hi) << 16 | (uint32_t)__half_as_ushort(lo);
}

// ---------------- A pre-convert: fp32 -> fp16 (hi only; 2-product scheme) ----------------
__global__ void cvtA16_kernel(const float4* __restrict__ A, uint2* __restrict__ Ah, int n4)
{
    int i = blockIdx.x * blockDim.x + threadIdx.x;
    if (i >= n4) return;
    float4 a = A[i];
    Ah[i] = make_uint2(pack2(__float2half_rn(a.x), __float2half_rn(a.y)),
                       pack2(__float2half_rn(a.z), __float2half_rn(a.w)));
}

// ---------------- W [K,N] -> WhT/WlT (fp16 split) + WT (fp32), transposed [N,K] ----------------
__global__ void splitW_kernel(const float* __restrict__ W,
                              __half* __restrict__ WhT, __half* __restrict__ WlT,
                              float* __restrict__ WT, int K, int N)
{
    __shared__ float tile[32][33];
    int n0 = blockIdx.x * 32, k0 = blockIdx.y * 32;
    for (int r = threadIdx.y; r < 32; r += 8)
        tile[r][threadIdx.x] = W[(size_t)(k0 + r) * N + n0 + threadIdx.x];
    __syncthreads();
    for (int r = threadIdx.y; r < 32; r += 8) {
        float v = tile[threadIdx.x][r];
        __half h = __float2half_rn(v);
        size_t idx = (size_t)(n0 + r) * K + k0 + threadIdx.x;
        WhT[idx] = h;
        WlT[idx] = __float2half_rn(v - __half2float(h));
        WT[idx]  = v;
    }
}

// ---------------- generic fast GEMM: C[M,512] = A[M,K](f16) @ (Bh+Bl)[512,K]^T ----------------
__global__ __launch_bounds__(512, 1)
void hgemm_kernel(const __half* __restrict__ A, const __half* __restrict__ Bh,
                  const __half* __restrict__ Bl, float* __restrict__ C, int K)
{
    extern __shared__ __half hsm[];
    const int tid = threadIdx.x;
    const int wid = tid >> 5, lane = tid & 31;
    const int gid = lane >> 2, tg = lane & 3;
    const int warp_m = wid >> 2;            // 0..3 -> 32-row slab
    const int warp_n = wid & 3;             // 0..3 -> 64-col slab
    const size_t mrow0 = (size_t)blockIdx.y * HBM;
    const size_t ncol0 = (size_t)blockIdx.x * HBN;
    const int nch = K / HBK;

    float acc[2][8][4];
#pragma unroll
    for (int i = 0; i < 2; i++)
#pragma unroll
        for (int j = 0; j < 8; j++)
#pragma unroll
            for (int q = 0; q < 4; q++) acc[i][j][q] = 0.0f;

    auto load_chunk = [&](int c) {
        __half* sb = hsm + (c % NSTAGE) * H_STAGE;
        const int k0 = c * HBK;
#pragma unroll
        for (int i = tid; i < 2560; i += 512) {
            if (i < 512) {                       // A tile: 128 rows x 4 granules
                int r = i >> 2, g = i & 3;
                cp16(s2u(sb + r * HSTR + g * 8), A + (mrow0 + r) * K + k0 + g * 8);
            } else {                             // Bh/Bl: 2 x 256 rows x 4 granules
                int ii = i - 512;
                int m = ii >> 10;
                int r = (ii >> 2) & 255, g = ii & 3;
                const __half* src = (m ? Bl : Bh) + (ncol0 + r) * K + k0 + g * 8;
                cp16(s2u(sb + (m ? H_OFF_B1 : H_OFF_B0) + r * HSTR + g * 8), src);
            }
        }
        asm volatile("cp.async.commit_group;" ::: "memory");
    };

    for (int c0 = 0; c0 < NSTAGE && c0 < nch; c0++) load_chunk(c0);

    for (int c = 0; c < nch; c++) {
        const __half* sb = hsm + (c % NSTAGE) * H_STAGE;
        int rem = nch - 1 - c;                   // groups allowed to stay pending
        if (rem >= 3)      asm volatile("cp.async.wait_group 3;" ::: "memory");
        else if (rem == 2) asm volatile("cp.async.wait_group 2;" ::: "memory");
        else if (rem == 1) asm volatile("cp.async.wait_group 1;" ::: "memory");
        else               asm volatile("cp.async.wait_group 0;" ::: "memory");
        __syncthreads();

        const __half* sA  = sb;
        const __half* sBh = sb + H_OFF_B0;
        const __half* sBl = sb + H_OFF_B1;

#pragma unroll
        for (int ks = 0; ks < 2; ks++) {
            const int k0 = ks * 16;
            uint32_t ah[2][4];
#pragma unroll
            for (int i = 0; i < 2; i++) {
                int m0 = warp_m * 32 + i * 16 + gid;
                ah[i][0] = *(const uint32_t*)(sA +  m0      * HSTR + k0 + 2*tg);
                ah[i][1] = *(const uint32_t*)(sA + (m0 + 8) * HSTR + k0 + 2*tg);
                ah[i][2] = *(const uint32_t*)(sA +  m0      * HSTR + k0 + 2*tg + 8);
                ah[i][3] = *(const uint32_t*)(sA + (m0 + 8) * HSTR + k0 + 2*tg + 8);
            }
#pragma unroll
            for (int j = 0; j < 8; j++) {
                int n0 = warp_n * 64 + j * 8 + gid;
                uint32_t bh0 = *(const uint32_t*)(sBh + n0 * HSTR + k0 + 2*tg);
                uint32_t bh1 = *(const uint32_t*)(sBh + n0 * HSTR + k0 + 2*tg + 8);
                uint32_t bl0 = *(const uint32_t*)(sBl + n0 * HSTR + k0 + 2*tg);
                uint32_t bl1 = *(const uint32_t*)(sBl + n0 * HSTR + k0 + 2*tg + 8);
#pragma unroll
                for (int i = 0; i < 2; i++) {
                    hmma16(acc[i][j], ah[i], bh0, bh1);
                    hmma16(acc[i][j], ah[i], bl0, bl1);
                }
            }
        }
        __syncthreads();
        if (c + NSTAGE < nch) load_chunk(c + NSTAGE);
    }

#pragma unroll
    for (int i = 0; i < 2; i++) {
        size_t m0 = mrow0 + warp_m * 32 + i * 16 + gid;
#pragma unroll
        for (int j = 0; j < 8; j++) {
            size_t n0 = ncol0 + warp_n * 64 + j * 8 + 2 * tg;
            *(float2*)(C +  m0      * FUS + n0) = make_float2(acc[i][j][0], acc[i][j][1]);
            *(float2*)(C + (m0 + 8) * FUS + n0) = make_float2(acc[i][j][2], acc[i][j][3]);
        }
    }
}

// ---------------- dual fp32 SGEMM (prox + trunk; R4 bit-identical arithmetic) ----------------
template<int BM, int BN, int BK, int TM, int TN>
__global__ __launch_bounds__((BM/TM)*(BN/TN))
void sgemm_dual(const float* __restrict__ A0, const float* __restrict__ B0, float* __restrict__ C0,
                const float* __restrict__ A1, const float* __restrict__ B1, float* __restrict__ C1,
                int M, int N, int K)
{
    const float* A = blockIdx.z ? A1 : A0;
    const float* B = blockIdx.z ? B1 : B0;
    float*       C = blockIdx.z ? C1 : C0;

    const int NT = (BM/TM)*(BN/TN);
    __shared__ float As[BK][BM + 1];
    __shared__ float Bs[BK][BN];

    const int tid  = threadIdx.x;
    const int tcol = tid % (BN/TN);
    const int trow = tid / (BN/TN);

    const float* Ab = A + (size_t)blockIdx.y * BM * K;
    const float* Bb = B + blockIdx.x * BN;

    float acc[TM][TN];
#pragma unroll
    for (int i = 0; i < TM; i++)
#pragma unroll
        for (int j = 0; j < TN; j++) acc[i][j] = 0.0f;

    for (int k0 = 0; k0 < K; k0 += BK) {
#pragma unroll
        for (int i = tid; i < BM*BK/4; i += NT) {
            int row = i / (BK/4);
            int kc  = (i % (BK/4)) * 4;
            float4 v = *(const float4*)(Ab + (size_t)row * K + k0 + kc);
            As[kc+0][row] = v.x; As[kc+1][row] = v.y;
            As[kc+2][row] = v.z; As[kc+3][row] = v.w;
        }
#pragma unroll
        for (int i = tid; i < BK*BN/4; i += NT) {
            int row = i / (BN/4);
            int nc  = (i % (BN/4)) * 4;
            *(float4*)(&Bs[row][nc]) = *(const float4*)(Bb + (size_t)(k0+row) * N + nc);
        }
        __syncthreads();

#pragma unroll
        for (int kk = 0; kk < BK; kk++) {
            float ar[TM], br[TN];
#pragma unroll
            for (int ii = 0; ii < TM; ii++) ar[ii] = As[kk][trow*TM + ii];
#pragma unroll
            for (int jj = 0; jj < TN; jj++) br[jj] = Bs[kk][tcol*TN + jj];
#pragma unroll
            for (int ii = 0; ii < TM; ii++)
#pragma unroll
                for (int jj = 0; jj < TN; jj++)
                    acc[ii][jj] = fmaf(ar[ii], br[jj], acc[ii][jj]);
        }
        __syncthreads();
    }

    float* Cb = C + (size_t)(blockIdx.y*BM + trow*TM) * N + blockIdx.x*BN + tcol*TN;
#pragma unroll
    for (int ii = 0; ii < TM; ii++)
#pragma unroll
        for (int jj = 0; jj < TN; jj++)
            Cb[(size_t)ii * N + jj] = acc[ii][jj];
}

// ---------------- all-steps proximal / trunk LIF (stores per-step states) ----------------
__global__ void lif_pt_all_kernel(const float* __restrict__ prox,
                                  const float* __restrict__ trunk,
                                  float* __restrict__ pall, float* __restrict__ tall)
{
    int i = blockIdx.x * blockDim.x + threadIdx.x;
    if (i >= BATCH * FUS) return;
    float pv = 0.0f, tv = 0.0f;
#pragma unroll
    for (int t = 0; t < T_WIN; t++) {
        pv = __fadd_rn(pv, __fmul_rn(__fsub_rn(prox [t*BATCH*FUS + i], pv), 0.5f));
        tv = __fadd_rn(tv, __fmul_rn(__fsub_rn(trunk[t*BATCH*FUS + i], tv), 0.5f));
        pall[t*BATCH*FUS + i] = pv;
        tall[t*BATCH*FUS + i] = tv;
    }
}

// ---------------- fused 4-step soma + spike (uchar + half) + near-threshold flags ------------
__global__ void soma_fast_kernel(const float* __restrict__ dist,
                                 const float* __restrict__ pall, const float* __restrict__ tall,
                                 unsigned char* __restrict__ spk, __half* __restrict__ spkh,
                                 unsigned char* __restrict__ flag)
{
    int i = blockIdx.x * blockDim.x + threadIdx.x;     // over NELEM/4
    if (i >= NELEM / 4) return;
    int fi4 = i & (FUS/4 - 1);
    int n   = i >> 7;
    int b   = n >> 6;

    float4 dv = make_float4(0,0,0,0), sv = make_float4(0,0,0,0);
    float pm[4] = {0,0,0,0};
    uchar4 fl = make_uchar4(0,0,0,0);

#pragma unroll
    for (int t = 0; t < T_WIN; t++) {
        float4 dd = ((const float4*)(dist + (size_t)t*NELEM))[i];
        float4 pv = ((const float4*)(pall + t*BATCH*FUS))[b * (FUS/4) + fi4];
        float4 tv = ((const float4*)(tall + t*BATCH*FUS))[b * (FUS/4) + fi4];
        uchar4 sp;
#define LIF_STEP(c, q)                                                          \
        {                                                                       \
            dv.c = __fadd_rn(dv.c, __fmul_rn(__fsub_rn(dd.c, dv.c), 0.5f));     \
            float u = __fsub_rn(__fadd_rn(__fmul_rn(pv.c, dv.c), tv.c), sv.c);  \
            float spre = __fadd_rn(sv.c, __fmul_rn(u, 0.5f));                   \
            float ap = fabsf(pv.c); if (ap > pm[q]) pm[q] = ap;                 \
            if (fabsf(spre - 0.5f) < (1.0f + pm[q]) * DELTA0) fl.c = 1;         \
            sp.c = (spre >= 0.5f) ? 1 : 0;                                      \
            sv.c = sp.c ? 0.0f : spre;                                          \
        }
        LIF_STEP(x, 0) LIF_STEP(y, 1) LIF_STEP(z, 2) LIF_STEP(w, 3)
#undef LIF_STEP
        ((uchar4*)(spk + (size_t)t*NELEM))[i] = sp;
        uint2 hv;
        hv.x = (sp.y ? 0x3C000000u : 0u) | (sp.x ? 0x3C00u : 0u);
        hv.y = (sp.w ? 0x3C000000u : 0u) | (sp.z ? 0x3C00u : 0u);
        ((uint2*)(spkh + (size_t)t*NELEM))[i] = hv;
    }
    ((uchar4*)flag)[i] = fl;
}

// ---------------- repair1: exact R4 chains for flagged soma elements ----------------
__global__ __launch_bounds__(256)
void repair_kernel(const float* __restrict__ tau, const float* __restrict__ WT,
                   const float* __restrict__ pall, const float* __restrict__ tall,
                   const unsigned char* __restrict__ flag,
                   unsigned char* __restrict__ spk, __half* __restrict__ spkh)
{
    int e = blockIdx.x * blockDim.x + threadIdx.x;     // NELEM threads exactly
    unsigned char fl = flag[e];
    if (__ballot_sync(0xffffffffu, (unsigned)fl) == 0u) return;
    if (!fl) return;

    int n = e >> 9;          // FUS = 512
    int f = e & (FUS - 1);
    int b = n >> 6;

    const float4* w  = (const float4*)(WT + (size_t)f * DIN);
    const float4* a0 = (const float4*)(tau + ((size_t)0 * BSROWS + n) * DIN);
    const float4* a1 = (const float4*)(tau + ((size_t)1 * BSROWS + n) * DIN);
    const float4* a2 = (const float4*)(tau + ((size_t)2 * BSROWS + n) * DIN);
    const float4* a3 = (const float4*)(tau + ((size_t)3 * BSROWS + n) * DIN);

    float s0 = 0.0f, s1 = 0.0f, s2 = 0.0f, s3 = 0.0f;
    for (int k = 0; k < DIN / 4; k++) {
        float4 wv = w[k];
        float4 v0 = a0[k], v1 = a1[k], v2 = a2[k], v3 = a3[k];
        s0 = fmaf(v0.x, wv.x, s0); s0 = fmaf(v0.y, wv.y, s0);
        s0 = fmaf(v0.z, wv.z, s0); s0 = fmaf(v0.w, wv.w, s0);
        s1 = fmaf(v1.x, wv.x, s1); s1 = fmaf(v1.y, wv.y, s1);
        s1 = fmaf(v1.z, wv.z, s1); s1 = fmaf(v1.w, wv.w, s1);
        s2 = fmaf(v2.x, wv.x, s2); s2 = fmaf(v2.y, wv.y, s2);
        s2 = fmaf(v2.z, wv.z, s2); s2 = fmaf(v2.w, wv.w, s2);
        s3 = fmaf(v3.x, wv.x, s3); s3 = fmaf(v3.y, wv.y, s3);
        s3 = fmaf(v3.z, wv.z, s3); s3 = fmaf(v3.w, wv.w, s3);
    }
    float dists[T_WIN] = {s0, s1, s2, s3};

    float dv = 0.0f, sv = 0.0f;
#pragma unroll
    for (int t = 0; t < T_WIN; t++) {
        float pv = pall[t*BATCH*FUS + b * FUS + f];
        float tv = tall[t*BATCH*FUS + b * FUS + f];
        dv = __fadd_rn(dv, __fmul_rn(__fsub_rn(dists[t], dv), 0.5f));
        float u = __fsub_rn(__fadd_rn(__fmul_rn(pv, dv), tv), sv);
        float spre = __fadd_rn(sv, __fmul_rn(u, 0.5f));
        unsigned char sb = (spre >= 0.5f) ? 1 : 0;
        sv = sb ? 0.0f : spre;
        size_t idx = (size_t)t*NELEM + (size_t)n * FUS + f;
        spk[idx]  = sb;
        spkh[idx] = __ushort_as_half(sb ? (unsigned short)0x3C00 : (unsigned short)0);
    }
}

// ---------------- fused 4-step layer-2 LIF from hfast + flags ----------------
__global__ void lif2_kernel(const float* __restrict__ hfast, const float* __restrict__ b1,
                            unsigned char* __restrict__ hs4, unsigned char* __restrict__ flag2)
{
    int i = blockIdx.x * blockDim.x + threadIdx.x;     // over NELEM/4 (n = i>>7, c = (i&127)*4)
    if (i >= NELEM / 4) return;
    float4 bv = ((const float4*)b1)[i & 127];
    float4 lm = make_float4(0,0,0,0);
    uchar4 fl = make_uchar4(0,0,0,0);

#pragma unroll
    for (int t = 0; t < T_WIN; t++) {
        float4 hv = ((const float4*)(hfast + (size_t)t*NELEM))[i];
        uchar4 sp;
#define L2_STEP(c)                                                              \
        {                                                                       \
            float h = __fadd_rn(hv.c, bv.c);                                    \
            lm.c = __fadd_rn(lm.c, __fmul_rn(__fsub_rn(h, lm.c), 0.5f));        \
            if (fabsf(lm.c - 0.5f) < DELTA2) fl.c = 1;                          \
            sp.c = (lm.c >= 0.5f) ? 1 : 0;                                      \
            if (sp.c) lm.c = 0.0f;                                              \
        }
        L2_STEP(x) L2_STEP(y) L2_STEP(z) L2_STEP(w)
#undef L2_STEP
        ((uchar4*)(hs4 + (size_t)t*NELEM))[i] = sp;
    }
    ((uchar4*)flag2)[i] = fl;
}

// ---------------- repair2: exact R4 layer-2 chains for flagged (n,c) ----------------
__global__ __launch_bounds__(256)
void repair2_kernel(const unsigned char* __restrict__ spk, const float* __restrict__ W1T,
                    const float* __restrict__ b1, const unsigned char* __restrict__ flag2,
                    unsigned char* __restrict__ hs4)
{
    int e = blockIdx.x * blockDim.x + threadIdx.x;     // NELEM threads
    unsigned char fl = flag2[e];
    if (__ballot_sync(0xffffffffu, (unsigned)fl) == 0u) return;
    if (!fl) return;

    int n = e >> 9;
    int c = e & (HID - 1);
    const float4* wc = (const float4*)(W1T + (size_t)c * FUS);
    float b1c = b1[c];

    float lm = 0.0f;
#pragma unroll
    for (int t = 0; t < T_WIN; t++) {
        const uchar4* sr = (const uchar4*)(spk + (size_t)t*NELEM + (size_t)n * FUS);
        float acc = 0.0f;
        for (int k = 0; k < FUS / 4; k++) {
            uchar4 s = sr[k];
            float4 wv = wc[k];
            acc = fmaf((float)s.x, wv.x, acc);
            acc = fmaf((float)s.y, wv.y, acc);
            acc = fmaf((float)s.z, wv.z, acc);
            acc = fmaf((float)s.w, wv.w, acc);
        }
        float h = __fadd_rn(acc, b1c);
        lm = __fadd_rn(lm, __fmul_rn(__fsub_rn(h, lm), 0.5f));
        unsigned char sb = (lm >= 0.5f) ? 1 : 0;
        if (sb) lm = 0.0f;
        hs4[(size_t)t*NELEM + (size_t)n * FUS + c] = sb;
    }
}

// ---------------- fused output: outacc[n,:] = sum_t (hs4[t][n,:] @ W2 + b2) ----------------
__global__ __launch_bounds__(256)
void out_fused_kernel(const unsigned char* __restrict__ hs4, const float* __restrict__ W2,
                      const float* __restrict__ b2, float* __restrict__ outacc)
{
    __shared__ float W2s[HID * NLAST];
    for (int i = threadIdx.x; i < HID * NLAST; i += blockDim.x) W2s[i] = W2[i];
    __syncthreads();

    int warp = threadIdx.x >> 5;
    int lane = threadIdx.x & 31;
    int n = blockIdx.x * 8 + warp;

    float res[NLAST];
#pragma unroll
    for (int t = 0; t < T_WIN; t++) {
        uint4 v = ((const uint4*)(hs4 + (size_t)t*NELEM + (size_t)n * HID))[lane];
        const unsigned char* pb = (const unsigned char*)&v;
        float acc[NLAST];
#pragma unroll
        for (int l = 0; l < NLAST; l++) acc[l] = 0.0f;
#pragma unroll
        for (int jj = 0; jj < 16; jj++) {
            if (pb[jj]) {
                const float* wrow = &W2s[(lane * 16 + jj) * NLAST];
#pragma unroll
                for (int l = 0; l < NLAST; l++) acc[l] += wrow[l];
            }
        }
#pragma unroll
        for (int off = 16; off > 0; off >>= 1)
#pragma unroll
            for (int l = 0; l < NLAST; l++)
                acc[l] += __shfl_down_sync(0xffffffffu, acc[l], off);
#pragma unroll
        for (int l = 0; l < NLAST; l++) {
            float val = __fadd_rn(acc[l], b2[l]);
            res[l] = (t == 0) ? val : __fadd_rn(res[l], val);
        }
    }
    if (lane == 0) {
        float* dst = outacc + (size_t)n * NLAST;
#pragma unroll
        for (int l = 0; l < NLAST; l++) dst[l] = res[l];
    }
}

// ---------------- final: mean over T, reshape [B,S,L] -> [B,L,S] ----------------
__global__ void final_kernel(const float* __restrict__ outacc, float* __restrict__ out)
{
    int i = blockIdx.x * blockDim.x + threadIdx.x;
    if (i >= BATCH * NLAST * SEQ) return;
    int s = i % SEQ;
    int l = (i / SEQ) % NLAST;
    int b = i / (SEQ * NLAST);
    int n = b * SEQ + s;
    out[i] = __fmul_rn(outacc[(size_t)n * NLAST + l], 0.25f);
}

// ---------------- launcher ----------------
extern "C" void kernel_launch(void* const* d_in, const int* in_sizes, int n_in,
                              void* d_out, int out_size)
{
    const float* state = (const float*)d_in[0];
    const float* tau   = (const float*)d_in[1];
    const float* event = (const float*)d_in[2];
    const float* Wp    = (const float*)d_in[3];
    const float* Wd    = (const float*)d_in[4];
    const float* Wt    = (const float*)d_in[5];
    const float* W1    = (const float*)d_in[6];
    const float* b1    = (const float*)d_in[7];
    const float* W2    = (const float*)d_in[8];
    const float* b2    = (const float*)d_in[9];
    float* out = (float*)d_out;

    __half *Ah, *WhT, *WlT, *W1hT, *W1lT, *spkh;
    float *WT, *W1T, *dist, *hfast, *prox, *trunk, *pall, *tall, *outacc;
    unsigned char *spk, *flag, *hs4, *flag2;
    cudaGetSymbolAddress((void**)&Ah,     g_Ah);
    cudaGetSymbolAddress((void**)&WhT,    g_WhT);
    cudaGetSymbolAddress((void**)&WlT,    g_WlT);
    cudaGetSymbolAddress((void**)&WT,     g_WT);
    cudaGetSymbolAddress((void**)&W1hT,   g_W1hT);
    cudaGetSymbolAddress((void**)&W1lT,   g_W1lT);
    cudaGetSymbolAddress((void**)&W1T,    g_W1T);
    cudaGetSymbolAddress((void**)&dist,   g_dist);
    cudaGetSymbolAddress((void**)&hfast,  g_hfast);
    cudaGetSymbolAddress((void**)&prox,   g_prox);
    cudaGetSymbolAddress((void**)&trunk,  g_trunk);
    cudaGetSymbolAddress((void**)&pall,   g_pall);
    cudaGetSymbolAddress((void**)&tall,   g_tall);
    cudaGetSymbolAddress((void**)&spk,    g_spk);
    cudaGetSymbolAddress((void**)&spkh,   g_spkh);
    cudaGetSymbolAddress((void**)&flag,   g_flag);
    cudaGetSymbolAddress((void**)&hs4,    g_hs4);
    cudaGetSymbolAddress((void**)&flag2,  g_flag2);
    cudaGetSymbolAddress((void**)&outacc, g_outacc);

    cudaFuncSetAttribute(hgemm_kernel,
                         cudaFuncAttributeMaxDynamicSharedMemorySize, HGEMM_SMEM);

    // Launch order arranged so the dist hgemm is launch index 3 (the profiled one).
    {
        int n4 = MROWS * DIN / 4;
        cvtA16_kernel<<<n4 / 256, 256>>>((const float4*)tau, (uint2*)Ah, n4);                // 0
    }
    splitW_kernel<<<dim3(FUS/32, DIN/32), dim3(32, 8)>>>(Wd, WhT, WlT, WT, DIN, FUS);        // 1
    sgemm_dual<64,64,16,4,4><<<dim3(FUS/64, (T_WIN*BATCH)/64, 2), 256>>>(
        state, Wp, prox, event, Wt, trunk, T_WIN*BATCH, FUS, DIN);                           // 2
    hgemm_kernel<<<dim3(FUS/HBN, MROWS/HBM), 512, HGEMM_SMEM>>>(Ah, WhT, WlT, dist, DIN);    // 3 (profiled)
    splitW_kernel<<<dim3(HID/32, FUS/32), dim3(32, 8)>>>(W1, W1hT, W1lT, W1T, FUS, HID);     // 4
    lif_pt_all_kernel<<<(BATCH*FUS)/256, 256>>>(prox, trunk, pall, tall);                    // 5
    soma_fast_kernel<<<(NELEM/4)/256, 256>>>(dist, pall, tall, spk, spkh, flag);             // 6
    repair_kernel<<<NELEM/256, 256>>>(tau, WT, pall, tall, flag, spk, spkh);                 // 7
    hgemm_kernel<<<dim3(HID/HBN, MROWS/HBM), 512, HGEMM_SMEM>>>(spkh, W1hT, W1lT, hfast, FUS); // 8
    lif2_kernel<<<(NELEM/4)/256, 256>>>(hfast, b1, hs4, flag2);                              // 9
    repair2_kernel<<<NELEM/256, 256>>>(spk, W1T, b1, flag2, hs4);                            // 10
    out_fused_kernel<<<BSROWS/8, 256>>>(hs4, W2, b2, outacc);                                // 11
    final_kernel<<<(BATCH*NLAST*SEQ + 255)/256, 256>>>(outacc, out);                         // 12
}

// round 13
// speedup vs baseline: 1.7095x; 1.7095x over previous
#include <cuda_runtime.h>
#include <cuda_fp16.h>
#include <cstdint>

// ---------------- problem constants ----------------
#define T_WIN 4
#define BATCH 128
#define SEQ   64
#define BSROWS 8192           // BATCH*SEQ
#define DIN   3136
#define FUS   512
#define HID   512
#define NLAST 18
#define MROWS (T_WIN*BSROWS)  // 32768
#define NELEM (BSROWS*FUS)    // 4,194,304 soma elements

// ---------------- fp16 GEMM tiling ----------------
#define HBM 128
#define HBN 256
#define HBK 32
#define HSTR 40                              // halves per smem row (32 + 8 pad)

// 3-product (dist): A, Al, Bh, Bl tiles
#define T3_OFF_AL (128*HSTR)
#define T3_OFF_BH (256*HSTR)
#define T3_OFF_BL (512*HSTR)
#define T3_STAGE  (768*HSTR)                 // 30720 halves = 61440 B
#define NSTAGE3 3
#define HGEMM3_SMEM (NSTAGE3*T3_STAGE*2)     // 184320 B

// 2-product (layer 2): A, Bh, Bl tiles
#define T2_OFF_B0 (128*HSTR)
#define T2_OFF_B1 ((128+256)*HSTR)
#define T2_STAGE  ((128+512)*HSTR)           // 25600 halves = 51200 B
#define NSTAGE2 4
#define HGEMM2_SMEM (NSTAGE2*T2_STAGE*2)     // 204800 B

#define DELTA0 5e-4f          // soma flag band (3-product reorder err max ~3e-5 -> 17x margin)
#define DELTA2 2e-4f          // layer-2 flag band (h err ~3e-6)

// ---------------- scratch (device globals; no allocations allowed) ----------------
__device__ __half        g_Ah  [(size_t)MROWS * DIN];             // 205 MiB (fp16-hi of tau)
__device__ __half        g_Al  [(size_t)MROWS * DIN];             // 205 MiB (fp16-lo of tau)
__device__ __half        g_WhT [(size_t)FUS * DIN];               // W_dist^T fp16-hi
__device__ __half        g_WlT [(size_t)FUS * DIN];               // W_dist^T fp16-lo
__device__ float         g_WT  [(size_t)FUS * DIN];               // exact fp32 W_dist^T (repair1)
__device__ __half        g_W1hT[(size_t)HID * FUS];               // W1^T fp16-hi
__device__ __half        g_W1lT[(size_t)HID * FUS];               // W1^T fp16-lo
__device__ float         g_W1T [(size_t)HID * FUS];               // exact fp32 W1^T (repair2)
__device__ float         g_dist [(size_t)T_WIN * BSROWS * FUS];   // 64 MiB
__device__ float         g_hfast[(size_t)MROWS * HID];            // 64 MiB
__device__ float         g_prox [T_WIN * BATCH * FUS];
__device__ float         g_trunk[T_WIN * BATCH * FUS];
__device__ float         g_pall [T_WIN * BATCH * FUS];
__device__ float         g_tall [T_WIN * BATCH * FUS];
__device__ unsigned char g_spk  [(size_t)T_WIN * NELEM];          // layer-1 spikes
__device__ __half        g_spkh [(size_t)T_WIN * NELEM];          // same, fp16 for MMA
__device__ unsigned char g_flag [NELEM];
__device__ unsigned char g_hs4  [(size_t)T_WIN * NELEM];          // layer-2 spikes
__device__ unsigned char g_flag2[NELEM];
__device__ float         g_outacc[BSROWS * NLAST];

// ---------------- helpers ----------------
__device__ __forceinline__ uint32_t s2u(const void* p) {
    uint32_t a;
    asm("{ .reg .u64 t; cvta.to.shared.u64 t, %1; cvt.u32.u64 %0, t; }" : "=r"(a) : "l"(p));
    return a;
}
__device__ __forceinline__ void cp16(uint32_t dst, const void* src) {
    asm volatile("cp.async.cg.shared.global [%0], [%1], 16;" :: "r"(dst), "l"(src));
}
__device__ __forceinline__ void hmma16(float* c, const uint32_t* a, uint32_t b0, uint32_t b1) {
    asm volatile(
        "mma.sync.aligned.m16n8k16.row.col.f32.f16.f16.f32 "
        "{%0,%1,%2,%3}, {%4,%5,%6,%7}, {%8,%9}, {%0,%1,%2,%3};"
        : "+f"(c[0]), "+f"(c[1]), "+f"(c[2]), "+f"(c[3])
        : "r"(a[0]), "r"(a[1]), "r"(a[2]), "r"(a[3]), "r"(b0), "r"(b1));
}
__device__ __forceinline__ uint32_t pack2(__half lo, __half hi) {
    return (uint32_t)__half_as_ushort(hi) << 16 | (uint32_t)__half_as_ushort(lo);
}

// ---------------- A pre-split: fp32 -> (hi, lo) fp16 ----------------
__global__ void splitA16_kernel(const float4* __restrict__ A,
                                uint2* __restrict__ Ah, uint2* __restrict__ Al, int n4)
{
    int i = blockIdx.x * blockDim.x + threadIdx.x;
    if (i >= n4) return;
    float4 a = A[i];
    __half hx = __float2half_rn(a.x), hy = __float2half_rn(a.y);
    __half hz = __float2half_rn(a.z), hw = __float2half_rn(a.w);
    Ah[i] = make_uint2(pack2(hx, hy), pack2(hz, hw));
    Al[i] = make_uint2(pack2(__float2half_rn(a.x - __half2float(hx)),
                             __float2half_rn(a.y - __half2float(hy))),
                       pack2(__float2half_rn(a.z - __half2float(hz)),
                             __float2half_rn(a.w - __half2float(hw))));
}

// ---------------- W [K,N] -> WhT/WlT (fp16 split) + WT (fp32), transposed [N,K] ----------------
__global__ void splitW_kernel(const float* __restrict__ W,
                              __half* __restrict__ WhT, __half* __restrict__ WlT,
                              float* __restrict__ WT, int K, int N)
{
    __shared__ float tile[32][33];
    int n0 = blockIdx.x * 32, k0 = blockIdx.y * 32;
    for (int r = threadIdx.y; r < 32; r += 8)
        tile[r][threadIdx.x] = W[(size_t)(k0 + r) * N + n0 + threadIdx.x];
    __syncthreads();
    for (int r = threadIdx.y; r < 32; r += 8) {
        float v = tile[threadIdx.x][r];
        __half h = __float2half_rn(v);
        size_t idx = (size_t)(n0 + r) * K + k0 + threadIdx.x;
        WhT[idx] = h;
        WlT[idx] = __float2half_rn(v - __half2float(h));
        WT[idx]  = v;
    }
}

// ---------------- 3-product GEMM: C[M,512] = (Ah+Al)[M,K] @ (Bh+Bl)[512,K]^T (drop Al*Bl) ------
__global__ __launch_bounds__(512, 1)
void hgemm3_kernel(const __half* __restrict__ Ah, const __half* __restrict__ Al,
                   const __half* __restrict__ Bh, const __half* __restrict__ Bl,
                   float* __restrict__ C, int K)
{
    extern __shared__ __half hsm[];
    const int tid = threadIdx.x;
    const int wid = tid >> 5, lane = tid & 31;
    const int gid = lane >> 2, tg = lane & 3;
    const int warp_m = wid >> 2;
    const int warp_n = wid & 3;
    const size_t mrow0 = (size_t)blockIdx.y * HBM;
    const size_t ncol0 = (size_t)blockIdx.x * HBN;
    const int nch = K / HBK;

    float acc[2][8][4];
#pragma unroll
    for (int i = 0; i < 2; i++)
#pragma unroll
        for (int j = 0; j < 8; j++)
#pragma unroll
            for (int q = 0; q < 4; q++) acc[i][j][q] = 0.0f;

    auto load_chunk = [&](int c) {
        __half* sb = hsm + (c % NSTAGE3) * T3_STAGE;
        const int k0 = c * HBK;
#pragma unroll
        for (int i = tid; i < 3072; i += 512) {
            if (i < 1024) {                      // Ah/Al: 2 x 128 rows x 4 granules
                int m = i >> 9;
                int r = (i >> 2) & 127, g = i & 3;
                const __half* src = (m ? Al : Ah) + (mrow0 + r) * K + k0 + g * 8;
                cp16(s2u(sb + (m ? T3_OFF_AL : 0) + r * HSTR + g * 8), src);
            } else {                             // Bh/Bl: 2 x 256 rows x 4 granules
                int ii = i - 1024;
                int m = ii >> 10;
                int r = (ii >> 2) & 255, g = ii & 3;
                const __half* src = (m ? Bl : Bh) + (ncol0 + r) * K + k0 + g * 8;
                cp16(s2u(sb + (m ? T3_OFF_BL : T3_OFF_BH) + r * HSTR + g * 8), src);
            }
        }
        asm volatile("cp.async.commit_group;" ::: "memory");
    };

    load_chunk(0);
    load_chunk(1);
    load_chunk(2);

    for (int c = 0; c < nch; c++) {
        const __half* sb = hsm + (c % NSTAGE3) * T3_STAGE;
        int rem = nch - 1 - c;
        if (rem >= 2)      asm volatile("cp.async.wait_group 2;" ::: "memory");
        else if (rem == 1) asm volatile("cp.async.wait_group 1;" ::: "memory");
        else               asm volatile("cp.async.wait_group 0;" ::: "memory");
        __syncthreads();

        const __half* sAh = sb;
        const __half* sAl = sb + T3_OFF_AL;
        const __half* sBh = sb + T3_OFF_BH;
        const __half* sBl = sb + T3_OFF_BL;

#pragma unroll
        for (int ks = 0; ks < 2; ks++) {
            const int k0 = ks * 16;
            uint32_t ah[2][4], al[2][4];
#pragma unroll
            for (int i = 0; i < 2; i++) {
                int m0 = warp_m * 32 + i * 16 + gid;
                ah[i][0] = *(const uint32_t*)(sAh +  m0      * HSTR + k0 + 2*tg);
                ah[i][1] = *(const uint32_t*)(sAh + (m0 + 8) * HSTR + k0 + 2*tg);
                ah[i][2] = *(const uint32_t*)(sAh +  m0      * HSTR + k0 + 2*tg + 8);
                ah[i][3] = *(const uint32_t*)(sAh + (m0 + 8) * HSTR + k0 + 2*tg + 8);
                al[i][0] = *(const uint32_t*)(sAl +  m0      * HSTR + k0 + 2*tg);
                al[i][1] = *(const uint32_t*)(sAl + (m0 + 8) * HSTR + k0 + 2*tg);
                al[i][2] = *(const uint32_t*)(sAl +  m0      * HSTR + k0 + 2*tg + 8);
                al[i][3] = *(const uint32_t*)(sAl + (m0 + 8) * HSTR + k0 + 2*tg + 8);
            }
#pragma unroll
            for (int j = 0; j < 8; j++) {
                int n0 = warp_n * 64 + j * 8 + gid;
                uint32_t bh0 = *(const uint32_t*)(sBh + n0 * HSTR + k0 + 2*tg);
                uint32_t bh1 = *(const uint32_t*)(sBh + n0 * HSTR + k0 + 2*tg + 8);
                uint32_t bl0 = *(const uint32_t*)(sBl + n0 * HSTR + k0 + 2*tg);
                uint32_t bl1 = *(const uint32_t*)(sBl + n0 * HSTR + k0 + 2*tg + 8);
#pragma unroll
                for (int i = 0; i < 2; i++) {
                    hmma16(acc[i][j], ah[i], bh0, bh1);
                    hmma16(acc[i][j], ah[i], bl0, bl1);
                    hmma16(acc[i][j], al[i], bh0, bh1);
                }
            }
        }
        __syncthreads();
        if (c + NSTAGE3 < nch) load_chunk(c + NSTAGE3);
    }

#pragma unroll
    for (int i = 0; i < 2; i++) {
        size_t m0 = mrow0 + warp_m * 32 + i * 16 + gid;
#pragma unroll
        for (int j = 0; j < 8; j++) {
            size_t n0 = ncol0 + warp_n * 64 + j * 8 + 2 * tg;
            *(float2*)(C +  m0      * FUS + n0) = make_float2(acc[i][j][0], acc[i][j][1]);
            *(float2*)(C + (m0 + 8) * FUS + n0) = make_float2(acc[i][j][2], acc[i][j][3]);
        }
    }
}

// ---------------- 2-product GEMM: C[M,512] = A[M,K](f16, exact) @ (Bh+Bl)[512,K]^T ------------
__global__ __launch_bounds__(512, 1)
void hgemm2_kernel(const __half* __restrict__ A, const __half* __restrict__ Bh,
                   const __half* __restrict__ Bl, float* __restrict__ C, int K)
{
    extern __shared__ __half hsm[];
    const int tid = threadIdx.x;
    const int wid = tid >> 5, lane = tid & 31;
    const int gid = lane >> 2, tg = lane & 3;
    const int warp_m = wid >> 2;
    const int warp_n = wid & 3;
    const size_t mrow0 = (size_t)blockIdx.y * HBM;
    const size_t ncol0 = (size_t)blockIdx.x * HBN;
    const int nch = K / HBK;

    float acc[2][8][4];
#pragma unroll
    for (int i = 0; i < 2; i++)
#pragma unroll
        for (int j = 0; j < 8; j++)
#pragma unroll
            for (int q = 0; q < 4; q++) acc[i][j][q] = 0.0f;

    auto load_chunk = [&](int c) {
        __half* sb = hsm + (c % NSTAGE2) * T2_STAGE;
        const int k0 = c * HBK;
#pragma unroll
        for (int i = tid; i < 2560; i += 512) {
            if (i < 512) {
                int r = i >> 2, g = i & 3;
                cp16(s2u(sb + r * HSTR + g * 8), A + (mrow0 + r) * K + k0 + g * 8);
            } else {
                int ii = i - 512;
                int m = ii >> 10;
                int r = (ii >> 2) & 255, g = ii & 3;
                const __half* src = (m ? Bl : Bh) + (ncol0 + r) * K + k0 + g * 8;
                cp16(s2u(sb + (m ? T2_OFF_B1 : T2_OFF_B0) + r * HSTR + g * 8), src);
            }
        }
        asm volatile("cp.async.commit_group;" ::: "memory");
    };

    for (int c0 = 0; c0 < NSTAGE2 && c0 < nch; c0++) load_chunk(c0);

    for (int c = 0; c < nch; c++) {
        const __half* sb = hsm + (c % NSTAGE2) * T2_STAGE;
        int rem = nch - 1 - c;
        if (rem >= 3)      asm volatile("cp.async.wait_group 3;" ::: "memory");
        else if (rem == 2) asm volatile("cp.async.wait_group 2;" ::: "memory");
        else if (rem == 1) asm volatile("cp.async.wait_group 1;" ::: "memory");
        else               asm volatile("cp.async.wait_group 0;" ::: "memory");
        __syncthreads();

        const __half* sA  = sb;
        const __half* sBh = sb + T2_OFF_B0;
        const __half* sBl = sb + T2_OFF_B1;

#pragma unroll
        for (int ks = 0; ks < 2; ks++) {
            const int k0 = ks * 16;
            uint32_t ah[2][4];
#pragma unroll
            for (int i = 0; i < 2; i++) {
                int m0 = warp_m * 32 + i * 16 + gid;
                ah[i][0] = *(const uint32_t*)(sA +  m0      * HSTR + k0 + 2*tg);
                ah[i][1] = *(const uint32_t*)(sA + (m0 + 8) * HSTR + k0 + 2*tg);
                ah[i][2] = *(const uint32_t*)(sA +  m0      * HSTR + k0 + 2*tg + 8);
                ah[i][3] = *(const uint32_t*)(sA + (m0 + 8) * HSTR + k0 + 2*tg + 8);
            }
#pragma unroll
            for (int j = 0; j < 8; j++) {
                int n0 = warp_n * 64 + j * 8 + gid;
                uint32_t bh0 = *(const uint32_t*)(sBh + n0 * HSTR + k0 + 2*tg);
                uint32_t bh1 = *(const uint32_t*)(sBh + n0 * HSTR + k0 + 2*tg + 8);
                uint32_t bl0 = *(const uint32_t*)(sBl + n0 * HSTR + k0 + 2*tg);
                uint32_t bl1 = *(const uint32_t*)(sBl + n0 * HSTR + k0 + 2*tg + 8);
#pragma unroll
                for (int i = 0; i < 2; i++) {
                    hmma16(acc[i][j], ah[i], bh0, bh1);
                    hmma16(acc[i][j], ah[i], bl0, bl1);
                }
            }
        }
        __syncthreads();
        if (c + NSTAGE2 < nch) load_chunk(c + NSTAGE2);
    }

#pragma unroll
    for (int i = 0; i < 2; i++) {
        size_t m0 = mrow0 + warp_m * 32 + i * 16 + gid;
#pragma unroll
        for (int j = 0; j < 8; j++) {
            size_t n0 = ncol0 + warp_n * 64 + j * 8 + 2 * tg;
            *(float2*)(C +  m0      * FUS + n0) = make_float2(acc[i][j][0], acc[i][j][1]);
            *(float2*)(C + (m0 + 8) * FUS + n0) = make_float2(acc[i][j][2], acc[i][j][3]);
        }
    }
}

// ---------------- dual fp32 SGEMM (prox + trunk; R4 bit-identical arithmetic) ----------------
template<int BM, int BN, int BK, int TM, int TN>
__global__ __launch_bounds__((BM/TM)*(BN/TN))
void sgemm_dual(const float* __restrict__ A0, const float* __restrict__ B0, float* __restrict__ C0,
                const float* __restrict__ A1, const float* __restrict__ B1, float* __restrict__ C1,
                int M, int N, int K)
{
    const float* A = blockIdx.z ? A1 : A0;
    const float* B = blockIdx.z ? B1 : B0;
    float*       C = blockIdx.z ? C1 : C0;

    const int NT = (BM/TM)*(BN/TN);
    __shared__ float As[BK][BM + 1];
    __shared__ float Bs[BK][BN];

    const int tid  = threadIdx.x;
    const int tcol = tid % (BN/TN);
    const int trow = tid / (BN/TN);

    const float* Ab = A + (size_t)blockIdx.y * BM * K;
    const float* Bb = B + blockIdx.x * BN;

    float acc[TM][TN];
#pragma unroll
    for (int i = 0; i < TM; i++)
#pragma unroll
        for (int j = 0; j < TN; j++) acc[i][j] = 0.0f;

    for (int k0 = 0; k0 < K; k0 += BK) {
#pragma unroll
        for (int i = tid; i < BM*BK/4; i += NT) {
            int row = i / (BK/4);
            int kc  = (i % (BK/4)) * 4;
            float4 v = *(const float4*)(Ab + (size_t)row * K + k0 + kc);
            As[kc+0][row] = v.x; As[kc+1][row] = v.y;
            As[kc+2][row] = v.z; As[kc+3][row] = v.w;
        }
#pragma unroll
        for (int i = tid; i < BK*BN/4; i += NT) {
            int row = i / (BN/4);
            int nc  = (i % (BN/4)) * 4;
            *(float4*)(&Bs[row][nc]) = *(const float4*)(Bb + (size_t)(k0+row) * N + nc);
        }
        __syncthreads();

#pragma unroll
        for (int kk = 0; kk < BK; kk++) {
            float ar[TM], br[TN];
#pragma unroll
            for (int ii = 0; ii < TM; ii++) ar[ii] = As[kk][trow*TM + ii];
#pragma unroll
            for (int jj = 0; jj < TN; jj++) br[jj] = Bs[kk][tcol*TN + jj];
#pragma unroll
            for (int ii = 0; ii < TM; ii++)
#pragma unroll
                for (int jj = 0; jj < TN; jj++)
                    acc[ii][jj] = fmaf(ar[ii], br[jj], acc[ii][jj]);
        }
        __syncthreads();
    }

    float* Cb = C + (size_t)(blockIdx.y*BM + trow*TM) * N + blockIdx.x*BN + tcol*TN;
#pragma unroll
    for (int ii = 0; ii < TM; ii++)
#pragma unroll
        for (int jj = 0; jj < TN; jj++)
            Cb[(size_t)ii * N + jj] = acc[ii][jj];
}

// ---------------- all-steps proximal / trunk LIF (stores per-step states) ----------------
__global__ void lif_pt_all_kernel(const float* __restrict__ prox,
                                  const float* __restrict__ trunk,
                                  float* __restrict__ pall, float* __restrict__ tall)
{
    int i = blockIdx.x * blockDim.x + threadIdx.x;
    if (i >= BATCH * FUS) return;
    float pv = 0.0f, tv = 0.0f;
#pragma unroll
    for (int t = 0; t < T_WIN; t++) {
        pv = __fadd_rn(pv, __fmul_rn(__fsub_rn(prox [t*BATCH*FUS + i], pv), 0.5f));
        tv = __fadd_rn(tv, __fmul_rn(__fsub_rn(trunk[t*BATCH*FUS + i], tv), 0.5f));
        pall[t*BATCH*FUS + i] = pv;
        tall[t*BATCH*FUS + i] = tv;
    }
}

// ---------------- fused 4-step soma + spike (uchar + half) + flat flag band ----------------
__global__ void soma_fast_kernel(const float* __restrict__ dist,
                                 const float* __restrict__ pall, const float* __restrict__ tall,
                                 unsigned char* __restrict__ spk, __half* __restrict__ spkh,
                                 unsigned char* __restrict__ flag)
{
    int i = blockIdx.x * blockDim.x + threadIdx.x;     // over NELEM/4
    if (i >= NELEM / 4) return;
    int fi4 = i & (FUS/4 - 1);
    int n   = i >> 7;
    int b   = n >> 6;

    float4 dv = make_float4(0,0,0,0), sv = make_float4(0,0,0,0);
    uchar4 fl = make_uchar4(0,0,0,0);

#pragma unroll
    for (int t = 0; t < T_WIN; t++) {
        float4 dd = ((const float4*)(dist + (size_t)t*NELEM))[i];
        float4 pv = ((const float4*)(pall + t*BATCH*FUS))[b * (FUS/4) + fi4];
        float4 tv = ((const float4*)(tall + t*BATCH*FUS))[b * (FUS/4) + fi4];
        uchar4 sp;
#define LIF_STEP(c)                                                             \
        {                                                                       \
            dv.c = __fadd_rn(dv.c, __fmul_rn(__fsub_rn(dd.c, dv.c), 0.5f));     \
            float u = __fsub_rn(__fadd_rn(__fmul_rn(pv.c, dv.c), tv.c), sv.c);  \
            float spre = __fadd_rn(sv.c, __fmul_rn(u, 0.5f));                   \
            if (fabsf(spre - 0.5f) < DELTA0) fl.c = 1;                          \
            sp.c = (spre >= 0.5f) ? 1 : 0;                                      \
            sv.c = sp.c ? 0.0f : spre;                                          \
        }
        LIF_STEP(x) LIF_STEP(y) LIF_STEP(z) LIF_STEP(w)
#undef LIF_STEP
        ((uchar4*)(spk + (size_t)t*NELEM))[i] = sp;
        uint2 hv;
        hv.x = (sp.y ? 0x3C000000u : 0u) | (sp.x ? 0x3C00u : 0u);
        hv.y = (sp.w ? 0x3C000000u : 0u) | (sp.z ? 0x3C00u : 0u);
        ((uint2*)(spkh + (size_t)t*NELEM))[i] = hv;
    }
    ((uchar4*)flag)[i] = fl;
}

// ---------------- repair1: exact R4 chains for flagged soma elements ----------------
__global__ __launch_bounds__(256)
void repair_kernel(const float* __restrict__ tau, const float* __restrict__ WT,
                   const float* __restrict__ pall, const float* __restrict__ tall,
                   const unsigned char* __restrict__ flag,
                   unsigned char* __restrict__ spk, __half* __restrict__ spkh)
{
    int e = blockIdx.x * blockDim.x + threadIdx.x;     // NELEM threads exactly
    unsigned char fl = flag[e];
    if (__ballot_sync(0xffffffffu, (unsigned)fl) == 0u) return;
    if (!fl) return;

    int n = e >> 9;          // FUS = 512
    int f = e & (FUS - 1);
    int b = n >> 6;

    const float4* w  = (const float4*)(WT + (size_t)f * DIN);
    const float4* a0 = (const float4*)(tau + ((size_t)0 * BSROWS + n) * DIN);
    const float4* a1 = (const float4*)(tau + ((size_t)1 * BSROWS + n) * DIN);
    const float4* a2 = (const float4*)(tau + ((size_t)2 * BSROWS + n) * DIN);
    const float4* a3 = (const float4*)(tau + ((size_t)3 * BSROWS + n) * DIN);

    float s0 = 0.0f, s1 = 0.0f, s2 = 0.0f, s3 = 0.0f;
#pragma unroll 2
    for (int k = 0; k < DIN / 4; k++) {
        float4 wv = w[k];
        float4 v0 = a0[k], v1 = a1[k], v2 = a2[k], v3 = a3[k];
        s0 = fmaf(v0.x, wv.x, s0); s0 = fmaf(v0.y, wv.y, s0);
        s0 = fmaf(v0.z, wv.z, s0); s0 = fmaf(v0.w, wv.w, s0);
        s1 = fmaf(v1.x, wv.x, s1); s1 = fmaf(v1.y, wv.y, s1);
        s1 = fmaf(v1.z, wv.z, s1); s1 = fmaf(v1.w, wv.w, s1);
        s2 = fmaf(v2.x, wv.x, s2); s2 = fmaf(v2.y, wv.y, s2);
        s2 = fmaf(v2.z, wv.z, s2); s2 = fmaf(v2.w, wv.w, s2);
        s3 = fmaf(v3.x, wv.x, s3); s3 = fmaf(v3.y, wv.y, s3);
        s3 = fmaf(v3.z, wv.z, s3); s3 = fmaf(v3.w, wv.w, s3);
    }
    float dists[T_WIN] = {s0, s1, s2, s3};

    float dv = 0.0f, sv = 0.0f;
#pragma unroll
    for (int t = 0; t < T_WIN; t++) {
        float pv = pall[t*BATCH*FUS + b * FUS + f];
        float tv = tall[t*BATCH*FUS + b * FUS + f];
        dv = __fadd_rn(dv, __fmul_rn(__fsub_rn(dists[t], dv), 0.5f));
        float u = __fsub_rn(__fadd_rn(__fmul_rn(pv, dv), tv), sv);
        float spre = __fadd_rn(sv, __fmul_rn(u, 0.5f));
        unsigned char sb = (spre >= 0.5f) ? 1 : 0;
        sv = sb ? 0.0f : spre;
        size_t idx = (size_t)t*NELEM + (size_t)n * FUS + f;
        spk[idx]  = sb;
        spkh[idx] = __ushort_as_half(sb ? (unsigned short)0x3C00 : (unsigned short)0);
    }
}

// ---------------- fused 4-step layer-2 LIF from hfast + flags ----------------
__global__ void lif2_kernel(const float* __restrict__ hfast, const float* __restrict__ b1,
                            unsigned char* __restrict__ hs4, unsigned char* __restrict__ flag2)
{
    int i = blockIdx.x * blockDim.x + threadIdx.x;     // over NELEM/4
    if (i >= NELEM / 4) return;
    float4 bv = ((const float4*)b1)[i & 127];
    float4 lm = make_float4(0,0,0,0);
    uchar4 fl = make_uchar4(0,0,0,0);

#pragma unroll
    for (int t = 0; t < T_WIN; t++) {
        float4 hv = ((const float4*)(hfast + (size_t)t*NELEM))[i];
        uchar4 sp;
#define L2_STEP(c)                                                              \
        {                                                                       \
            float h = __fadd_rn(hv.c, bv.c);                                    \
            lm.c = __fadd_rn(lm.c, __fmul_rn(__fsub_rn(h, lm.c), 0.5f));        \
            if (fabsf(lm.c - 0.5f) < DELTA2) fl.c = 1;                          \
            sp.c = (lm.c >= 0.5f) ? 1 : 0;                                      \
            if (sp.c) lm.c = 0.0f;                                              \
        }
        L2_STEP(x) L2_STEP(y) L2_STEP(z) L2_STEP(w)
#undef L2_STEP
        ((uchar4*)(hs4 + (size_t)t*NELEM))[i] = sp;
    }
    ((uchar4*)flag2)[i] = fl;
}

// ---------------- repair2: exact R4 layer-2 chains for flagged (n,c) ----------------
__global__ __launch_bounds__(256)
void repair2_kernel(const unsigned char* __restrict__ spk, const float* __restrict__ W1T,
                    const float* __restrict__ b1, const unsigned char* __restrict__ flag2,
                    unsigned char* __restrict__ hs4)
{
    int e = blockIdx.x * blockDim.x + threadIdx.x;     // NELEM threads
    unsigned char fl = flag2[e];
    if (__ballot_sync(0xffffffffu, (unsigned)fl) == 0u) return;
    if (!fl) return;

    int n = e >> 9;
    int c = e & (HID - 1);
    const float4* wc = (const float4*)(W1T + (size_t)c * FUS);
    float b1c = b1[c];

    float lm = 0.0f;
#pragma unroll
    for (int t = 0; t < T_WIN; t++) {
        const uchar4* sr = (const uchar4*)(spk + (size_t)t*NELEM + (size_t)n * FUS);
        float acc = 0.0f;
        for (int k = 0; k < FUS / 4; k++) {
            uchar4 s = sr[k];
            float4 wv = wc[k];
            acc = fmaf((float)s.x, wv.x, acc);
            acc = fmaf((float)s.y, wv.y, acc);
            acc = fmaf((float)s.z, wv.z, acc);
            acc = fmaf((float)s.w, wv.w, acc);
        }
        float h = __fadd_rn(acc, b1c);
        lm = __fadd_rn(lm, __fmul_rn(__fsub_rn(h, lm), 0.5f));
        unsigned char sb = (lm >= 0.5f) ? 1 : 0;
        if (sb) lm = 0.0f;
        hs4[(size_t)t*NELEM + (size_t)n * FUS + c] = sb;
    }
}

// ---------------- fused output: outacc[n,:] = sum_t (hs4[t][n,:] @ W2 + b2) ----------------
__global__ __launch_bounds__(256)
void out_fused_kernel(const unsigned char* __restrict__ hs4, const float* __restrict__ W2,
                      const float* __restrict__ b2, float* __restrict__ outacc)
{
    __shared__ float W2s[HID * NLAST];
    for (int i = threadIdx.x; i < HID * NLAST; i += blockDim.x) W2s[i] = W2[i];
    __syncthreads();

    int warp = threadIdx.x >> 5;
    int lane = threadIdx.x & 31;
    int n = blockIdx.x * 8 + warp;

    float res[NLAST];
#pragma unroll
    for (int t = 0; t < T_WIN; t++) {
        uint4 v = ((const uint4*)(hs4 + (size_t)t*NELEM + (size_t)n * HID))[lane];
        const unsigned char* pb = (const unsigned char*)&v;
        float acc[NLAST];
#pragma unroll
        for (int l = 0; l < NLAST; l++) acc[l] = 0.0f;
#pragma unroll
        for (int jj = 0; jj < 16; jj++) {
            if (pb[jj]) {
                const float* wrow = &W2s[(lane * 16 + jj) * NLAST];
#pragma unroll
                for (int l = 0; l < NLAST; l++) acc[l] += wrow[l];
            }
        }
#pragma unroll
        for (int off = 16; off > 0; off >>= 1)
#pragma unroll
            for (int l = 0; l < NLAST; l++)
                acc[l] += __shfl_down_sync(0xffffffffu, acc[l], off);
#pragma unroll
        for (int l = 0; l < NLAST; l++) {
            float val = __fadd_rn(acc[l], b2[l]);
            res[l] = (t == 0) ? val : __fadd_rn(res[l], val);
        }
    }
    if (lane == 0) {
        float* dst = outacc + (size_t)n * NLAST;
#pragma unroll
        for (int l = 0; l < NLAST; l++) dst[l] = res[l];
    }
}

// ---------------- final: mean over T, reshape [B,S,L] -> [B,L,S] ----------------
__global__ void final_kernel(const float* __restrict__ outacc, float* __restrict__ out)
{
    int i = blockIdx.x * blockDim.x + threadIdx.x;
    if (i >= BATCH * NLAST * SEQ) return;
    int s = i % SEQ;
    int l = (i / SEQ) % NLAST;
    int b = i / (SEQ * NLAST);
    int n = b * SEQ + s;
    out[i] = __fmul_rn(outacc[(size_t)n * NLAST + l], 0.25f);
}

// ---------------- launcher ----------------
extern "C" void kernel_launch(void* const* d_in, const int* in_sizes, int n_in,
                              void* d_out, int out_size)
{
    const float* state = (const float*)d_in[0];
    const float* tau   = (const float*)d_in[1];
    const float* event = (const float*)d_in[2];
    const float* Wp    = (const float*)d_in[3];
    const float* Wd    = (const float*)d_in[4];
    const float* Wt    = (const float*)d_in[5];
    const float* W1    = (const float*)d_in[6];
    const float* b1    = (const float*)d_in[7];
    const float* W2    = (const float*)d_in[8];
    const float* b2    = (const float*)d_in[9];
    float* out = (float*)d_out;

    __half *Ah, *Al, *WhT, *WlT, *W1hT, *W1lT, *spkh;
    float *WT, *W1T, *dist, *hfast, *prox, *trunk, *pall, *tall, *outacc;
    unsigned char *spk, *flag, *hs4, *flag2;
    cudaGetSymbolAddress((void**)&Ah,     g_Ah);
    cudaGetSymbolAddress((void**)&Al,     g_Al);
    cudaGetSymbolAddress((void**)&WhT,    g_WhT);
    cudaGetSymbolAddress((void**)&WlT,    g_WlT);
    cudaGetSymbolAddress((void**)&WT,     g_WT);
    cudaGetSymbolAddress((void**)&W1hT,   g_W1hT);
    cudaGetSymbolAddress((void**)&W1lT,   g_W1lT);
    cudaGetSymbolAddress((void**)&W1T,    g_W1T);
    cudaGetSymbolAddress((void**)&dist,   g_dist);
    cudaGetSymbolAddress((void**)&hfast,  g_hfast);
    cudaGetSymbolAddress((void**)&prox,   g_prox);
    cudaGetSymbolAddress((void**)&trunk,  g_trunk);
    cudaGetSymbolAddress((void**)&pall,   g_pall);
    cudaGetSymbolAddress((void**)&tall,   g_tall);
    cudaGetSymbolAddress((void**)&spk,    g_spk);
    cudaGetSymbolAddress((void**)&spkh,   g_spkh);
    cudaGetSymbolAddress((void**)&flag,   g_flag);
    cudaGetSymbolAddress((void**)&hs4,    g_hs4);
    cudaGetSymbolAddress((void**)&flag2,  g_flag2);
    cudaGetSymbolAddress((void**)&outacc, g_outacc);

    cudaFuncSetAttribute(hgemm3_kernel,
                         cudaFuncAttributeMaxDynamicSharedMemorySize, HGEMM3_SMEM);
    cudaFuncSetAttribute(hgemm2_kernel,
                         cudaFuncAttributeMaxDynamicSharedMemorySize, HGEMM2_SMEM);

    // Launch order arranged so the dist hgemm3 is launch index 3 (the profiled one).
    {
        int n4 = MROWS * DIN / 4;
        splitA16_kernel<<<n4 / 256, 256>>>((const float4*)tau, (uint2*)Ah, (uint2*)Al, n4);  // 0
    }
    splitW_kernel<<<dim3(FUS/32, DIN/32), dim3(32, 8)>>>(Wd, WhT, WlT, WT, DIN, FUS);        // 1
    sgemm_dual<64,64,16,4,4><<<dim3(FUS/64, (T_WIN*BATCH)/64, 2), 256>>>(
        state, Wp, prox, event, Wt, trunk, T_WIN*BATCH, FUS, DIN);                           // 2
    hgemm3_kernel<<<dim3(FUS/HBN, MROWS/HBM), 512, HGEMM3_SMEM>>>(Ah, Al, WhT, WlT, dist, DIN); // 3 (profiled)
    splitW_kernel<<<dim3(HID/32, FUS/32), dim3(32, 8)>>>(W1, W1hT, W1lT, W1T, FUS, HID);     // 4
    lif_pt_all_kernel<<<(BATCH*FUS)/256, 256>>>(prox, trunk, pall, tall);                    // 5
    soma_fast_kernel<<<(NELEM/4)/256, 256>>>(dist, pall, tall, spk, spkh, flag);             // 6
    repair_kernel<<<NELEM/256, 256>>>(tau, WT, pall, tall, flag, spk, spkh);                 // 7
    hgemm2_kernel<<<dim3(HID/HBN, MROWS/HBM), 512, HGEMM2_SMEM>>>(spkh, W1hT, W1lT, hfast, FUS); // 8
    lif2_kernel<<<(NELEM/4)/256, 256>>>(hfast, b1, hs4, flag2);                              // 9
    repair2_kernel<<<NELEM/256, 256>>>(spk, W1T, b1, flag2, hs4);                            // 10
    out_fused_kernel<<<BSROWS/8, 256>>>(hs4, W2, b2, outacc);                                // 11
    final_kernel<<<(BATCH*NLAST*SEQ + 255)/256, 256>>>(outacc, out);                         // 12
}

// round 14
// speedup vs baseline: 1.9308x; 1.1295x over previous
#include <cuda_runtime.h>
#include <cuda_fp16.h>
#include <cstdint>

// ---------------- problem constants ----------------
#define T_WIN 4
#define BATCH 128
#define SEQ   64
#define BSROWS 8192           // BATCH*SEQ
#define DIN   3136
#define FUS   512
#define HID   512
#define NLAST 18
#define MROWS (T_WIN*BSROWS)  // 32768
#define NELEM (BSROWS*FUS)    // 4,194,304 soma elements

// ---------------- fp16 GEMM tiling ----------------
#define HBM 128
#define HBN 256
#define HBK 32
#define HSTR 40                              // halves per smem row (32 + 8 pad)

// 3-product (dist): A, Al, Bh, Bl tiles
#define T3_OFF_AL (128*HSTR)
#define T3_OFF_BH (256*HSTR)
#define T3_OFF_BL (512*HSTR)
#define T3_STAGE  (768*HSTR)                 // 30720 halves = 61440 B
#define NSTAGE3 3
#define HGEMM3_SMEM (NSTAGE3*T3_STAGE*2)     // 184320 B

// 2-product (layer 2): A, Bh, Bl tiles
#define T2_OFF_B0 (128*HSTR)
#define T2_OFF_B1 ((128+256)*HSTR)
#define T2_STAGE  ((128+512)*HSTR)           // 25600 halves = 51200 B
#define NSTAGE2 4
#define HGEMM2_SMEM (NSTAGE2*T2_STAGE*2)     // 204800 B

#define DELTA0 2e-4f          // soma flag band (3-product reorder err max ~3e-5 -> ~6.7x margin)
#define DELTA2 2e-4f          // layer-2 flag band (h err max ~2e-5)

// ---------------- scratch (device globals; no allocations allowed) ----------------
__device__ __half        g_Ah  [(size_t)MROWS * DIN];             // fp16-hi of tau
__device__ __half        g_Al  [(size_t)MROWS * DIN];             // fp16-lo of tau
__device__ __half        g_WhT [(size_t)FUS * DIN];               // W_dist^T fp16-hi
__device__ __half        g_WlT [(size_t)FUS * DIN];               // W_dist^T fp16-lo
__device__ float         g_WT  [(size_t)FUS * DIN];               // exact fp32 W_dist^T (repair1)
__device__ __half        g_W1hT[(size_t)HID * FUS];               // W1^T fp16-hi
__device__ __half        g_W1lT[(size_t)HID * FUS];               // W1^T fp16-lo
__device__ float         g_W1T [(size_t)HID * FUS];               // exact fp32 W1^T (repair2)
__device__ float         g_dist [(size_t)T_WIN * BSROWS * FUS];   // 64 MiB
__device__ float         g_hfast[(size_t)MROWS * HID];            // 64 MiB
__device__ float         g_prox [T_WIN * BATCH * FUS];
__device__ float         g_trunk[T_WIN * BATCH * FUS];
__device__ float         g_pall [T_WIN * BATCH * FUS];
__device__ float         g_tall [T_WIN * BATCH * FUS];
__device__ unsigned char g_spk  [(size_t)T_WIN * NELEM];          // layer-1 spikes
__device__ __half        g_spkh [(size_t)T_WIN * NELEM];          // same, fp16 for MMA
__device__ unsigned char g_flag [NELEM];
__device__ unsigned char g_hs4  [(size_t)T_WIN * NELEM];          // layer-2 spikes
__device__ unsigned char g_flag2[NELEM];

// ---------------- helpers ----------------
__device__ __forceinline__ uint32_t s2u(const void* p) {
    uint32_t a;
    asm("{ .reg .u64 t; cvta.to.shared.u64 t, %1; cvt.u32.u64 %0, t; }" : "=r"(a) : "l"(p));
    return a;
}
__device__ __forceinline__ void cp16(uint32_t dst, const void* src) {
    asm volatile("cp.async.cg.shared.global [%0], [%1], 16;" :: "r"(dst), "l"(src));
}
__device__ __forceinline__ void hmma16(float* c, const uint32_t* a, uint32_t b0, uint32_t b1) {
    asm volatile(
        "mma.sync.aligned.m16n8k16.row.col.f32.f16.f16.f32 "
        "{%0,%1,%2,%3}, {%4,%5,%6,%7}, {%8,%9}, {%0,%1,%2,%3};"
        : "+f"(c[0]), "+f"(c[1]), "+f"(c[2]), "+f"(c[3])
        : "r"(a[0]), "r"(a[1]), "r"(a[2]), "r"(a[3]), "r"(b0), "r"(b1));
}
__device__ __forceinline__ uint32_t pack2(__half lo, __half hi) {
    return (uint32_t)__half_as_ushort(hi) << 16 | (uint32_t)__half_as_ushort(lo);
}

// ---------------- A pre-split: fp32 -> (hi, lo) fp16 ----------------
__global__ void splitA16_kernel(const float4* __restrict__ A,
                                uint2* __restrict__ Ah, uint2* __restrict__ Al, int n4)
{
    int i = blockIdx.x * blockDim.x + threadIdx.x;
    if (i >= n4) return;
    float4 a = A[i];
    __half hx = __float2half_rn(a.x), hy = __float2half_rn(a.y);
    __half hz = __float2half_rn(a.z), hw = __float2half_rn(a.w);
    Ah[i] = make_uint2(pack2(hx, hy), pack2(hz, hw));
    Al[i] = make_uint2(pack2(__float2half_rn(a.x - __half2float(hx)),
                             __float2half_rn(a.y - __half2float(hy))),
                       pack2(__float2half_rn(a.z - __half2float(hz)),
                             __float2half_rn(a.w - __half2float(hw))));
}

// ---------------- W [K,N] -> WhT/WlT (fp16 split) + WT (fp32), transposed [N,K] ----------------
__global__ void splitW_kernel(const float* __restrict__ W,
                              __half* __restrict__ WhT, __half* __restrict__ WlT,
                              float* __restrict__ WT, int K, int N)
{
    __shared__ float tile[32][33];
    int n0 = blockIdx.x * 32, k0 = blockIdx.y * 32;
    for (int r = threadIdx.y; r < 32; r += 8)
        tile[r][threadIdx.x] = W[(size_t)(k0 + r) * N + n0 + threadIdx.x];
    __syncthreads();
    for (int r = threadIdx.y; r < 32; r += 8) {
        float v = tile[threadIdx.x][r];
        __half h = __float2half_rn(v);
        size_t idx = (size_t)(n0 + r) * K + k0 + threadIdx.x;
        WhT[idx] = h;
        WlT[idx] = __float2half_rn(v - __half2float(h));
        WT[idx]  = v;
    }
}

// ---------------- 3-product GEMM: C[M,512] = (Ah+Al)[M,K] @ (Bh+Bl)[512,K]^T (drop Al*Bl) ------
__global__ __launch_bounds__(512, 1)
void hgemm3_kernel(const __half* __restrict__ Ah, const __half* __restrict__ Al,
                   const __half* __restrict__ Bh, const __half* __restrict__ Bl,
                   float* __restrict__ C, int K)
{
    extern __shared__ __half hsm[];
    const int tid = threadIdx.x;
    const int wid = tid >> 5, lane = tid & 31;
    const int gid = lane >> 2, tg = lane & 3;
    const int warp_m = wid >> 2;
    const int warp_n = wid & 3;
    const size_t mrow0 = (size_t)blockIdx.y * HBM;
    const size_t ncol0 = (size_t)blockIdx.x * HBN;
    const int nch = K / HBK;

    float acc[2][8][4];
#pragma unroll
    for (int i = 0; i < 2; i++)
#pragma unroll
        for (int j = 0; j < 8; j++)
#pragma unroll
            for (int q = 0; q < 4; q++) acc[i][j][q] = 0.0f;

    auto load_chunk = [&](int c) {
        __half* sb = hsm + (c % NSTAGE3) * T3_STAGE;
        const int k0 = c * HBK;
#pragma unroll
        for (int i = tid; i < 3072; i += 512) {
            if (i < 1024) {                      // Ah/Al: 2 x 128 rows x 4 granules
                int m = i >> 9;
                int r = (i >> 2) & 127, g = i & 3;
                const __half* src = (m ? Al : Ah) + (mrow0 + r) * K + k0 + g * 8;
                cp16(s2u(sb + (m ? T3_OFF_AL : 0) + r * HSTR + g * 8), src);
            } else {                             // Bh/Bl: 2 x 256 rows x 4 granules
                int ii = i - 1024;
                int m = ii >> 10;
                int r = (ii >> 2) & 255, g = ii & 3;
                const __half* src = (m ? Bl : Bh) + (ncol0 + r) * K + k0 + g * 8;
                cp16(s2u(sb + (m ? T3_OFF_BL : T3_OFF_BH) + r * HSTR + g * 8), src);
            }
        }
        asm volatile("cp.async.commit_group;" ::: "memory");
    };

    load_chunk(0);
    load_chunk(1);
    load_chunk(2);

    for (int c = 0; c < nch; c++) {
        const __half* sb = hsm + (c % NSTAGE3) * T3_STAGE;
        int rem = nch - 1 - c;
        if (rem >= 2)      asm volatile("cp.async.wait_group 2;" ::: "memory");
        else if (rem == 1) asm volatile("cp.async.wait_group 1;" ::: "memory");
        else               asm volatile("cp.async.wait_group 0;" ::: "memory");
        __syncthreads();

        const __half* sAh = sb;
        const __half* sAl = sb + T3_OFF_AL;
        const __half* sBh = sb + T3_OFF_BH;
        const __half* sBl = sb + T3_OFF_BL;

#pragma unroll
        for (int ks = 0; ks < 2; ks++) {
            const int k0 = ks * 16;
            uint32_t ah[2][4], al[2][4];
#pragma unroll
            for (int i = 0; i < 2; i++) {
                int m0 = warp_m * 32 + i * 16 + gid;
                ah[i][0] = *(const uint32_t*)(sAh +  m0      * HSTR + k0 + 2*tg);
                ah[i][1] = *(const uint32_t*)(sAh + (m0 + 8) * HSTR + k0 + 2*tg);
                ah[i][2] = *(const uint32_t*)(sAh +  m0      * HSTR + k0 + 2*tg + 8);
                ah[i][3] = *(const uint32_t*)(sAh + (m0 + 8) * HSTR + k0 + 2*tg + 8);
                al[i][0] = *(const uint32_t*)(sAl +  m0      * HSTR + k0 + 2*tg);
                al[i][1] = *(const uint32_t*)(sAl + (m0 + 8) * HSTR + k0 + 2*tg);
                al[i][2] = *(const uint32_t*)(sAl +  m0      * HSTR + k0 + 2*tg + 8);
                al[i][3] = *(const uint32_t*)(sAl + (m0 + 8) * HSTR + k0 + 2*tg + 8);
            }
#pragma unroll
            for (int j = 0; j < 8; j++) {
                int n0 = warp_n * 64 + j * 8 + gid;
                uint32_t bh0 = *(const uint32_t*)(sBh + n0 * HSTR + k0 + 2*tg);
                uint32_t bh1 = *(const uint32_t*)(sBh + n0 * HSTR + k0 + 2*tg + 8);
                uint32_t bl0 = *(const uint32_t*)(sBl + n0 * HSTR + k0 + 2*tg);
                uint32_t bl1 = *(const uint32_t*)(sBl + n0 * HSTR + k0 + 2*tg + 8);
#pragma unroll
                for (int i = 0; i < 2; i++) {
                    hmma16(acc[i][j], ah[i], bh0, bh1);
                    hmma16(acc[i][j], ah[i], bl0, bl1);
                    hmma16(acc[i][j], al[i], bh0, bh1);
                }
            }
        }
        __syncthreads();
        if (c + NSTAGE3 < nch) load_chunk(c + NSTAGE3);
    }

#pragma unroll
    for (int i = 0; i < 2; i++) {
        size_t m0 = mrow0 + warp_m * 32 + i * 16 + gid;
#pragma unroll
        for (int j = 0; j < 8; j++) {
            size_t n0 = ncol0 + warp_n * 64 + j * 8 + 2 * tg;
            *(float2*)(C +  m0      * FUS + n0) = make_float2(acc[i][j][0], acc[i][j][1]);
            *(float2*)(C + (m0 + 8) * FUS + n0) = make_float2(acc[i][j][2], acc[i][j][3]);
        }
    }
}

// ---------------- 2-product GEMM: C[M,512] = A[M,K](f16, exact) @ (Bh+Bl)[512,K]^T ------------
__global__ __launch_bounds__(512, 1)
void hgemm2_kernel(const __half* __restrict__ A, const __half* __restrict__ Bh,
                   const __half* __restrict__ Bl, float* __restrict__ C, int K)
{
    extern __shared__ __half hsm[];
    const int tid = threadIdx.x;
    const int wid = tid >> 5, lane = tid & 31;
    const int gid = lane >> 2, tg = lane & 3;
    const int warp_m = wid >> 2;
    const int warp_n = wid & 3;
    const size_t mrow0 = (size_t)blockIdx.y * HBM;
    const size_t ncol0 = (size_t)blockIdx.x * HBN;
    const int nch = K / HBK;

    float acc[2][8][4];
#pragma unroll
    for (int i = 0; i < 2; i++)
#pragma unroll
        for (int j = 0; j < 8; j++)
#pragma unroll
            for (int q = 0; q < 4; q++) acc[i][j][q] = 0.0f;

    auto load_chunk = [&](int c) {
        __half* sb = hsm + (c % NSTAGE2) * T2_STAGE;
        const int k0 = c * HBK;
#pragma unroll
        for (int i = tid; i < 2560; i += 512) {
            if (i < 512) {
                int r = i >> 2, g = i & 3;
                cp16(s2u(sb + r * HSTR + g * 8), A + (mrow0 + r) * K + k0 + g * 8);
            } else {
                int ii = i - 512;
                int m = ii >> 10;
                int r = (ii >> 2) & 255, g = ii & 3;
                const __half* src = (m ? Bl : Bh) + (ncol0 + r) * K + k0 + g * 8;
                cp16(s2u(sb + (m ? T2_OFF_B1 : T2_OFF_B0) + r * HSTR + g * 8), src);
            }
        }
        asm volatile("cp.async.commit_group;" ::: "memory");
    };

    for (int c0 = 0; c0 < NSTAGE2 && c0 < nch; c0++) load_chunk(c0);

    for (int c = 0; c < nch; c++) {
        const __half* sb = hsm + (c % NSTAGE2) * T2_STAGE;
        int rem = nch - 1 - c;
        if (rem >= 3)      asm volatile("cp.async.wait_group 3;" ::: "memory");
        else if (rem == 2) asm volatile("cp.async.wait_group 2;" ::: "memory");
        else if (rem == 1) asm volatile("cp.async.wait_group 1;" ::: "memory");
        else               asm volatile("cp.async.wait_group 0;" ::: "memory");
        __syncthreads();

        const __half* sA  = sb;
        const __half* sBh = sb + T2_OFF_B0;
        const __half* sBl = sb + T2_OFF_B1;

#pragma unroll
        for (int ks = 0; ks < 2; ks++) {
            const int k0 = ks * 16;
            uint32_t ah[2][4];
#pragma unroll
            for (int i = 0; i < 2; i++) {
                int m0 = warp_m * 32 + i * 16 + gid;
                ah[i][0] = *(const uint32_t*)(sA +  m0      * HSTR + k0 + 2*tg);
                ah[i][1] = *(const uint32_t*)(sA + (m0 + 8) * HSTR + k0 + 2*tg);
                ah[i][2] = *(const uint32_t*)(sA +  m0      * HSTR + k0 + 2*tg + 8);
                ah[i][3] = *(const uint32_t*)(sA + (m0 + 8) * HSTR + k0 + 2*tg + 8);
            }
#pragma unroll
            for (int j = 0; j < 8; j++) {
                int n0 = warp_n * 64 + j * 8 + gid;
                uint32_t bh0 = *(const uint32_t*)(sBh + n0 * HSTR + k0 + 2*tg);
                uint32_t bh1 = *(const uint32_t*)(sBh + n0 * HSTR + k0 + 2*tg + 8);
                uint32_t bl0 = *(const uint32_t*)(sBl + n0 * HSTR + k0 + 2*tg);
                uint32_t bl1 = *(const uint32_t*)(sBl + n0 * HSTR + k0 + 2*tg + 8);
#pragma unroll
                for (int i = 0; i < 2; i++) {
                    hmma16(acc[i][j], ah[i], bh0, bh1);
                    hmma16(acc[i][j], ah[i], bl0, bl1);
                }
            }
        }
        __syncthreads();
        if (c + NSTAGE2 < nch) load_chunk(c + NSTAGE2);
    }

#pragma unroll
    for (int i = 0; i < 2; i++) {
        size_t m0 = mrow0 + warp_m * 32 + i * 16 + gid;
#pragma unroll
        for (int j = 0; j < 8; j++) {
            size_t n0 = ncol0 + warp_n * 64 + j * 8 + 2 * tg;
            *(float2*)(C +  m0      * FUS + n0) = make_float2(acc[i][j][0], acc[i][j][1]);
            *(float2*)(C + (m0 + 8) * FUS + n0) = make_float2(acc[i][j][2], acc[i][j][3]);
        }
    }
}

// ---------------- dual fp32 SGEMM (prox + trunk; R4 bit-identical arithmetic) ----------------
template<int BM, int BN, int BK, int TM, int TN>
__global__ __launch_bounds__((BM/TM)*(BN/TN))
void sgemm_dual(const float* __restrict__ A0, const float* __restrict__ B0, float* __restrict__ C0,
                const float* __restrict__ A1, const float* __restrict__ B1, float* __restrict__ C1,
                int M, int N, int K)
{
    const float* A = blockIdx.z ? A1 : A0;
    const float* B = blockIdx.z ? B1 : B0;
    float*       C = blockIdx.z ? C1 : C0;

    const int NT = (BM/TM)*(BN/TN);
    __shared__ float As[BK][BM + 1];
    __shared__ float Bs[BK][BN];

    const int tid  = threadIdx.x;
    const int tcol = tid % (BN/TN);
    const int trow = tid / (BN/TN);

    const float* Ab = A + (size_t)blockIdx.y * BM * K;
    const float* Bb = B + blockIdx.x * BN;

    float acc[TM][TN];
#pragma unroll
    for (int i = 0; i < TM; i++)
#pragma unroll
        for (int j = 0; j < TN; j++) acc[i][j] = 0.0f;

    for (int k0 = 0; k0 < K; k0 += BK) {
#pragma unroll
        for (int i = tid; i < BM*BK/4; i += NT) {
            int row = i / (BK/4);
            int kc  = (i % (BK/4)) * 4;
            float4 v = *(const float4*)(Ab + (size_t)row * K + k0 + kc);
            As[kc+0][row] = v.x; As[kc+1][row] = v.y;
            As[kc+2][row] = v.z; As[kc+3][row] = v.w;
        }
#pragma unroll
        for (int i = tid; i < BK*BN/4; i += NT) {
            int row = i / (BN/4);
            int nc  = (i % (BN/4)) * 4;
            *(float4*)(&Bs[row][nc]) = *(const float4*)(Bb + (size_t)(k0+row) * N + nc);
        }
        __syncthreads();

#pragma unroll
        for (int kk = 0; kk < BK; kk++) {
            float ar[TM], br[TN];
#pragma unroll
            for (int ii = 0; ii < TM; ii++) ar[ii] = As[kk][trow*TM + ii];
#pragma unroll
            for (int jj = 0; jj < TN; jj++) br[jj] = Bs[kk][tcol*TN + jj];
#pragma unroll
            for (int ii = 0; ii < TM; ii++)
#pragma unroll
                for (int jj = 0; jj < TN; jj++)
                    acc[ii][jj] = fmaf(ar[ii], br[jj], acc[ii][jj]);
        }
        __syncthreads();
    }

    float* Cb = C + (size_t)(blockIdx.y*BM + trow*TM) * N + blockIdx.x*BN + tcol*TN;
#pragma unroll
    for (int ii = 0; ii < TM; ii++)
#pragma unroll
        for (int jj = 0; jj < TN; jj++)
            Cb[(size_t)ii * N + jj] = acc[ii][jj];
}

// ---------------- all-steps proximal / trunk LIF (stores per-step states) ----------------
__global__ void lif_pt_all_kernel(const float* __restrict__ prox,
                                  const float* __restrict__ trunk,
                                  float* __restrict__ pall, float* __restrict__ tall)
{
    int i = blockIdx.x * blockDim.x + threadIdx.x;
    if (i >= BATCH * FUS) return;
    float pv = 0.0f, tv = 0.0f;
#pragma unroll
    for (int t = 0; t < T_WIN; t++) {
        pv = __fadd_rn(pv, __fmul_rn(__fsub_rn(prox [t*BATCH*FUS + i], pv), 0.5f));
        tv = __fadd_rn(tv, __fmul_rn(__fsub_rn(trunk[t*BATCH*FUS + i], tv), 0.5f));
        pall[t*BATCH*FUS + i] = pv;
        tall[t*BATCH*FUS + i] = tv;
    }
}

// ---------------- fused 4-step soma + spike (uchar + half) + flat flag band ----------------
__global__ void soma_fast_kernel(const float* __restrict__ dist,
                                 const float* __restrict__ pall, const float* __restrict__ tall,
                                 unsigned char* __restrict__ spk, __half* __restrict__ spkh,
                                 unsigned char* __restrict__ flag)
{
    int i = blockIdx.x * blockDim.x + threadIdx.x;     // over NELEM/4
    if (i >= NELEM / 4) return;
    int fi4 = i & (FUS/4 - 1);
    int n   = i >> 7;
    int b   = n >> 6;

    float4 dv = make_float4(0,0,0,0), sv = make_float4(0,0,0,0);
    uchar4 fl = make_uchar4(0,0,0,0);

#pragma unroll
    for (int t = 0; t < T_WIN; t++) {
        float4 dd = ((const float4*)(dist + (size_t)t*NELEM))[i];
        float4 pv = ((const float4*)(pall + t*BATCH*FUS))[b * (FUS/4) + fi4];
        float4 tv = ((const float4*)(tall + t*BATCH*FUS))[b * (FUS/4) + fi4];
        uchar4 sp;
#define LIF_STEP(c)                                                             \
        {                                                                       \
            dv.c = __fadd_rn(dv.c, __fmul_rn(__fsub_rn(dd.c, dv.c), 0.5f));     \
            float u = __fsub_rn(__fadd_rn(__fmul_rn(pv.c, dv.c), tv.c), sv.c);  \
            float spre = __fadd_rn(sv.c, __fmul_rn(u, 0.5f));                   \
            if (fabsf(spre - 0.5f) < DELTA0) fl.c = 1;                          \
            sp.c = (spre >= 0.5f) ? 1 : 0;                                      \
            sv.c = sp.c ? 0.0f : spre;                                          \
        }
        LIF_STEP(x) LIF_STEP(y) LIF_STEP(z) LIF_STEP(w)
#undef LIF_STEP
        ((uchar4*)(spk + (size_t)t*NELEM))[i] = sp;
        uint2 hv;
        hv.x = (sp.y ? 0x3C000000u : 0u) | (sp.x ? 0x3C00u : 0u);
        hv.y = (sp.w ? 0x3C000000u : 0u) | (sp.z ? 0x3C00u : 0u);
        ((uint2*)(spkh + (size_t)t*NELEM))[i] = hv;
    }
    ((uchar4*)flag)[i] = fl;
}

// ---------------- repair1: exact R4 chains for flagged soma elements ----------------
__global__ __launch_bounds__(256)
void repair_kernel(const float* __restrict__ tau, const float* __restrict__ WT,
                   const float* __restrict__ pall, const float* __restrict__ tall,
                   const unsigned char* __restrict__ flag,
                   unsigned char* __restrict__ spk, __half* __restrict__ spkh)
{
    int e = blockIdx.x * blockDim.x + threadIdx.x;     // NELEM threads exactly
    unsigned char fl = flag[e];
    if (__ballot_sync(0xffffffffu, (unsigned)fl) == 0u) return;
    if (!fl) return;

    int n = e >> 9;          // FUS = 512
    int f = e & (FUS - 1);
    int b = n >> 6;

    const float4* w  = (const float4*)(WT + (size_t)f * DIN);
    const float4* a0 = (const float4*)(tau + ((size_t)0 * BSROWS + n) * DIN);
    const float4* a1 = (const float4*)(tau + ((size_t)1 * BSROWS + n) * DIN);
    const float4* a2 = (const float4*)(tau + ((size_t)2 * BSROWS + n) * DIN);
    const float4* a3 = (const float4*)(tau + ((size_t)3 * BSROWS + n) * DIN);

    float s0 = 0.0f, s1 = 0.0f, s2 = 0.0f, s3 = 0.0f;
#pragma unroll 2
    for (int k = 0; k < DIN / 4; k++) {
        float4 wv = w[k];
        float4 v0 = a0[k], v1 = a1[k], v2 = a2[k], v3 = a3[k];
        s0 = fmaf(v0.x, wv.x, s0); s0 = fmaf(v0.y, wv.y, s0);
        s0 = fmaf(v0.z, wv.z, s0); s0 = fmaf(v0.w, wv.w, s0);
        s1 = fmaf(v1.x, wv.x, s1); s1 = fmaf(v1.y, wv.y, s1);
        s1 = fmaf(v1.z, wv.z, s1); s1 = fmaf(v1.w, wv.w, s1);
        s2 = fmaf(v2.x, wv.x, s2); s2 = fmaf(v2.y, wv.y, s2);
        s2 = fmaf(v2.z, wv.z, s2); s2 = fmaf(v2.w, wv.w, s2);
        s3 = fmaf(v3.x, wv.x, s3); s3 = fmaf(v3.y, wv.y, s3);
        s3 = fmaf(v3.z, wv.z, s3); s3 = fmaf(v3.w, wv.w, s3);
    }
    float dists[T_WIN] = {s0, s1, s2, s3};

    float dv = 0.0f, sv = 0.0f;
#pragma unroll
    for (int t = 0; t < T_WIN; t++) {
        float pv = pall[t*BATCH*FUS + b * FUS + f];
        float tv = tall[t*BATCH*FUS + b * FUS + f];
        dv = __fadd_rn(dv, __fmul_rn(__fsub_rn(dists[t], dv), 0.5f));
        float u = __fsub_rn(__fadd_rn(__fmul_rn(pv, dv), tv), sv);
        float spre = __fadd_rn(sv, __fmul_rn(u, 0.5f));
        unsigned char sb = (spre >= 0.5f) ? 1 : 0;
        sv = sb ? 0.0f : spre;
        size_t idx = (size_t)t*NELEM + (size_t)n * FUS + f;
        spk[idx]  = sb;
        spkh[idx] = __ushort_as_half(sb ? (unsigned short)0x3C00 : (unsigned short)0);
    }
}

// ---------------- fused 4-step layer-2 LIF from hfast + flags ----------------
__global__ void lif2_kernel(const float* __restrict__ hfast, const float* __restrict__ b1,
                            unsigned char* __restrict__ hs4, unsigned char* __restrict__ flag2)
{
    int i = blockIdx.x * blockDim.x + threadIdx.x;     // over NELEM/4
    if (i >= NELEM / 4) return;
    float4 bv = ((const float4*)b1)[i & 127];
    float4 lm = make_float4(0,0,0,0);
    uchar4 fl = make_uchar4(0,0,0,0);

#pragma unroll
    for (int t = 0; t < T_WIN; t++) {
        float4 hv = ((const float4*)(hfast + (size_t)t*NELEM))[i];
        uchar4 sp;
#define L2_STEP(c)                                                              \
        {                                                                       \
            float h = __fadd_rn(hv.c, bv.c);                                    \
            lm.c = __fadd_rn(lm.c, __fmul_rn(__fsub_rn(h, lm.c), 0.5f));        \
            if (fabsf(lm.c - 0.5f) < DELTA2) fl.c = 1;                          \
            sp.c = (lm.c >= 0.5f) ? 1 : 0;                                      \
            if (sp.c) lm.c = 0.0f;                                              \
        }
        L2_STEP(x) L2_STEP(y) L2_STEP(z) L2_STEP(w)
#undef L2_STEP
        ((uchar4*)(hs4 + (size_t)t*NELEM))[i] = sp;
    }
    ((uchar4*)flag2)[i] = fl;
}

// ---------------- repair2: exact R4 layer-2 chains for flagged (n,c) ----------------
__global__ __launch_bounds__(256)
void repair2_kernel(const unsigned char* __restrict__ spk, const float* __restrict__ W1T,
                    const float* __restrict__ b1, const unsigned char* __restrict__ flag2,
                    unsigned char* __restrict__ hs4)
{
    int e = blockIdx.x * blockDim.x + threadIdx.x;     // NELEM threads
    unsigned char fl = flag2[e];
    if (__ballot_sync(0xffffffffu, (unsigned)fl) == 0u) return;
    if (!fl) return;

    int n = e >> 9;
    int c = e & (HID - 1);
    const float4* wc = (const float4*)(W1T + (size_t)c * FUS);
    float b1c = b1[c];

    float lm = 0.0f;
#pragma unroll
    for (int t = 0; t < T_WIN; t++) {
        const uchar4* sr = (const uchar4*)(spk + (size_t)t*NELEM + (size_t)n * FUS);
        float acc = 0.0f;
        for (int k = 0; k < FUS / 4; k++) {
            uchar4 s = sr[k];
            float4 wv = wc[k];
            acc = fmaf((float)s.x, wv.x, acc);
            acc = fmaf((float)s.y, wv.y, acc);
            acc = fmaf((float)s.z, wv.z, acc);
            acc = fmaf((float)s.w, wv.w, acc);
        }
        float h = __fadd_rn(acc, b1c);
        lm = __fadd_rn(lm, __fmul_rn(__fsub_rn(h, lm), 0.5f));
        unsigned char sb = (lm >= 0.5f) ? 1 : 0;
        if (sb) lm = 0.0f;
        hs4[(size_t)t*NELEM + (size_t)n * FUS + c] = sb;
    }
}

// ---------------- fused output (+final): out[b,l,s] = 0.25 * sum_t (hs4[t][n,:] @ W2 + b2) ----
__global__ __launch_bounds__(256)
void out_fused_kernel(const unsigned char* __restrict__ hs4, const float* __restrict__ W2,
                      const float* __restrict__ b2, float* __restrict__ out)
{
    __shared__ float W2s[HID * NLAST];
    for (int i = threadIdx.x; i < HID * NLAST; i += blockDim.x) W2s[i] = W2[i];
    __syncthreads();

    int warp = threadIdx.x >> 5;
    int lane = threadIdx.x & 31;
    int n = blockIdx.x * 8 + warp;
    int b = n >> 6;           // SEQ = 64
    int s = n & 63;

    float res[NLAST];
#pragma unroll
    for (int t = 0; t < T_WIN; t++) {
        uint4 v = ((const uint4*)(hs4 + (size_t)t*NELEM + (size_t)n * HID))[lane];
        const unsigned char* pb = (const unsigned char*)&v;
        float acc[NLAST];
#pragma unroll
        for (int l = 0; l < NLAST; l++) acc[l] = 0.0f;
#pragma unroll
        for (int jj = 0; jj < 16; jj++) {
            if (pb[jj]) {
                const float* wrow = &W2s[(lane * 16 + jj) * NLAST];
#pragma unroll
                for (int l = 0; l < NLAST; l++) acc[l] += wrow[l];
            }
        }
#pragma unroll
        for (int off = 16; off > 0; off >>= 1)
#pragma unroll
            for (int l = 0; l < NLAST; l++)
                acc[l] += __shfl_down_sync(0xffffffffu, acc[l], off);
#pragma unroll
        for (int l = 0; l < NLAST; l++) {
            float val = __fadd_rn(acc[l], b2[l]);
            res[l] = (t == 0) ? val : __fadd_rn(res[l], val);
        }
    }
    if (lane == 0) {
#pragma unroll
        for (int l = 0; l < NLAST; l++)
            out[((size_t)b * NLAST + l) * SEQ + s] = __fmul_rn(res[l], 0.25f);
    }
}

// ---------------- launcher ----------------
extern "C" void kernel_launch(void* const* d_in, const int* in_sizes, int n_in,
                              void* d_out, int out_size)
{
    const float* state = (const float*)d_in[0];
    const float* tau   = (const float*)d_in[1];
    const float* event = (const float*)d_in[2];
    const float* Wp    = (const float*)d_in[3];
    const float* Wd    = (const float*)d_in[4];
    const float* Wt    = (const float*)d_in[5];
    const float* W1    = (const float*)d_in[6];
    const float* b1    = (const float*)d_in[7];
    const float* W2    = (const float*)d_in[8];
    const float* b2    = (const float*)d_in[9];
    float* out = (float*)d_out;

    __half *Ah, *Al, *WhT, *WlT, *W1hT, *W1lT, *spkh;
    float *WT, *W1T, *dist, *hfast, *prox, *trunk, *pall, *tall;
    unsigned char *spk, *flag, *hs4, *flag2;
    cudaGetSymbolAddress((void**)&Ah,     g_Ah);
    cudaGetSymbolAddress((void**)&Al,     g_Al);
    cudaGetSymbolAddress((void**)&WhT,    g_WhT);
    cudaGetSymbolAddress((void**)&WlT,    g_WlT);
    cudaGetSymbolAddress((void**)&WT,     g_WT);
    cudaGetSymbolAddress((void**)&W1hT,   g_W1hT);
    cudaGetSymbolAddress((void**)&W1lT,   g_W1lT);
    cudaGetSymbolAddress((void**)&W1T,    g_W1T);
    cudaGetSymbolAddress((void**)&dist,   g_dist);
    cudaGetSymbolAddress((void**)&hfast,  g_hfast);
    cudaGetSymbolAddress((void**)&prox,   g_prox);
    cudaGetSymbolAddress((void**)&trunk,  g_trunk);
    cudaGetSymbolAddress((void**)&pall,   g_pall);
    cudaGetSymbolAddress((void**)&tall,   g_tall);
    cudaGetSymbolAddress((void**)&spk,    g_spk);
    cudaGetSymbolAddress((void**)&spkh,   g_spkh);
    cudaGetSymbolAddress((void**)&flag,   g_flag);
    cudaGetSymbolAddress((void**)&hs4,    g_hs4);
    cudaGetSymbolAddress((void**)&flag2,  g_flag2);

    cudaFuncSetAttribute(hgemm3_kernel,
                         cudaFuncAttributeMaxDynamicSharedMemorySize, HGEMM3_SMEM);
    cudaFuncSetAttribute(hgemm2_kernel,
                         cudaFuncAttributeMaxDynamicSharedMemorySize, HGEMM2_SMEM);

    // Launch order arranged so the dist hgemm3 is launch index 3 (the profiled one).
    {
        int n4 = MROWS * DIN / 4;
        splitA16_kernel<<<n4 / 256, 256>>>((const float4*)tau, (uint2*)Ah, (uint2*)Al, n4);  // 0
    }
    splitW_kernel<<<dim3(FUS/32, DIN/32), dim3(32, 8)>>>(Wd, WhT, WlT, WT, DIN, FUS);        // 1
    sgemm_dual<64,64,16,4,4><<<dim3(FUS/64, (T_WIN*BATCH)/64, 2), 256>>>(
        state, Wp, prox, event, Wt, trunk, T_WIN*BATCH, FUS, DIN);                           // 2
    hgemm3_kernel<<<dim3(FUS/HBN, MROWS/HBM), 512, HGEMM3_SMEM>>>(Ah, Al, WhT, WlT, dist, DIN); // 3 (profiled)
    splitW_kernel<<<dim3(HID/32, FUS/32), dim3(32, 8)>>>(W1, W1hT, W1lT, W1T, FUS, HID);     // 4
    lif_pt_all_kernel<<<(BATCH*FUS)/256, 256>>>(prox, trunk, pall, tall);                    // 5
    soma_fast_kernel<<<(NELEM/4)/256, 256>>>(dist, pall, tall, spk, spkh, flag);             // 6
    repair_kernel<<<NELEM/256, 256>>>(tau, WT, pall, tall, flag, spk, spkh);                 // 7
    hgemm2_kernel<<<dim3(HID/HBN, MROWS/HBM), 512, HGEMM2_SMEM>>>(spkh, W1hT, W1lT, hfast, FUS); // 8
    lif2_kernel<<<(NELEM/4)/256, 256>>>(hfast, b1, hs4, flag2);                              // 9
    repair2_kernel<<<NELEM/256, 256>>>(spk, W1T, b1, flag2, hs4);                            // 10
    out_fused_kernel<<<BSROWS/8, 256>>>(hs4, W2, b2, out);                                   // 11
}